// round 1
// baseline (speedup 1.0000x reference)
#include <cuda_runtime.h>

#define B_   2048
#define T_   200
#define D_   128
#define H_   128
#define M_   (B_ * T_)          // 409600 rows

typedef unsigned long long ull;

// ---------------- scratch (static device arrays; no allocation) ----------------
__device__ float g_Gx[(size_t)M_ * 256];   // x-part of gate pre-activations (+bg)
__device__ float g_Cx[(size_t)M_ * 128];   // x-part of candidate pre-activations (+bc)

// ---------------- f32x2 helpers (sm_103a packed FMA: 2x FFMA throughput) -------
__device__ __forceinline__ ull pack2(float x, float y) {
    ull r; asm("mov.b64 %0, {%1, %2};" : "=l"(r) : "f"(x), "f"(y)); return r;
}
__device__ __forceinline__ void unpack2(ull v, float& x, float& y) {
    asm("mov.b64 {%0, %1}, %2;" : "=f"(x), "=f"(y) : "l"(v));
}
__device__ __forceinline__ void fma2(ull& d, ull a, ull b) {
    asm("fma.rn.f32x2 %0, %1, %2, %0;" : "+l"(d) : "l"(a), "l"(b));
}
__device__ __forceinline__ float sigmoidf_(float x) {
    return 1.0f / (1.0f + __expf(-x));
}

// =============================================================================
// Kernel 1: precompute GEMM  [M,128] @ [128,384] -> Gx[M,256] (+bg), Cx[M,128] (+bc)
// Tile: 128(M) x 128(N), KC=16, 256 threads, thread tile 8x8 via f32x2 pairs (M-paired)
// =============================================================================
#define ASTRIDE 132   // padded row (floats), keeps 16B alignment, kills STS conflicts

__global__ void __launch_bounds__(256) augru_precompute(
    const float* __restrict__ X,    // [M,128]
    const float* __restrict__ Wg,   // [256,256]
    const float* __restrict__ bg,   // [256]
    const float* __restrict__ Wc,   // [256,128]
    const float* __restrict__ bc,   // [128]
    float* __restrict__ Gx,         // [M,256]
    float* __restrict__ Cx)         // [M,128]
{
    __shared__ float As[16][ASTRIDE];  // transposed A tile: As[k][m]
    __shared__ float Bs[16][128];      // Bs[k][n]

    const int tid = threadIdx.x;
    const int m0  = blockIdx.x * 128;
    const int nt  = blockIdx.y;        // 0,1 -> Wg cols; 2 -> Wc

    const float* W; int ldw, nc0; const float* bias; float* Out; int ldo;
    if (nt < 2) { W = Wg; ldw = 256; nc0 = nt * 128; bias = bg; Out = Gx; ldo = 256; }
    else        { W = Wc; ldw = 128; nc0 = 0;        bias = bc; Out = Cx; ldo = 128; }

    // warp 4x2 grid, lane 4x8 grid -> thread tile 8x8, warp tile 32x64
    const int w    = tid >> 5, lane = tid & 31;
    const int wm   = w & 3,    wn   = w >> 2;
    const int lm   = lane & 3, ln   = lane >> 2;
    const int tm8  = wm * 32 + lm * 8;
    const int tn8  = wn * 64 + ln * 8;

    ull acc[4][8];  // pairs over M: acc[p][j] = rows (tm8+2p, tm8+2p+1), col tn8+j
#pragma unroll
    for (int p = 0; p < 4; p++)
#pragma unroll
        for (int j = 0; j < 8; j++) acc[p][j] = 0ull;

    for (int k0 = 0; k0 < 128; k0 += 16) {
        // load A tile (128 m x 16 k), store transposed
#pragma unroll
        for (int q = 0; q < 2; q++) {
            int idx = tid + q * 256;
            int m = idx >> 2, c = idx & 3;
            float4 v = *(const float4*)&X[(size_t)(m0 + m) * 128 + k0 + c * 4];
            As[c * 4 + 0][m] = v.x; As[c * 4 + 1][m] = v.y;
            As[c * 4 + 2][m] = v.z; As[c * 4 + 3][m] = v.w;
        }
        // load B tile (16 k x 128 n)
#pragma unroll
        for (int q = 0; q < 2; q++) {
            int idx = tid + q * 256;
            int k = idx >> 5, n = (idx & 31) * 4;
            *(float4*)&Bs[k][n] = *(const float4*)&W[(size_t)(k0 + k) * ldw + nc0 + n];
        }
        __syncthreads();

#pragma unroll
        for (int k = 0; k < 16; k++) {
            ulonglong2 a01 = *(const ulonglong2*)&As[k][tm8];      // (m0,m1),(m2,m3)
            ulonglong2 a23 = *(const ulonglong2*)&As[k][tm8 + 4];  // (m4,m5),(m6,m7)
            float4 b0 = *(const float4*)&Bs[k][tn8];
            float4 b1 = *(const float4*)&Bs[k][tn8 + 4];
            ull ap[4] = {a01.x, a01.y, a23.x, a23.y};
            ull bd[8];
            bd[0] = pack2(b0.x, b0.x); bd[1] = pack2(b0.y, b0.y);
            bd[2] = pack2(b0.z, b0.z); bd[3] = pack2(b0.w, b0.w);
            bd[4] = pack2(b1.x, b1.x); bd[5] = pack2(b1.y, b1.y);
            bd[6] = pack2(b1.z, b1.z); bd[7] = pack2(b1.w, b1.w);
#pragma unroll
            for (int p = 0; p < 4; p++)
#pragma unroll
                for (int j = 0; j < 8; j++) fma2(acc[p][j], ap[p], bd[j]);
        }
        __syncthreads();
    }

    // epilogue: +bias, store
    float bl[8];
#pragma unroll
    for (int j = 0; j < 8; j++) bl[j] = bias[nc0 + tn8 + j];

#pragma unroll
    for (int p = 0; p < 4; p++) {
        float lo[8], hi[8];
#pragma unroll
        for (int j = 0; j < 8; j++) unpack2(acc[p][j], lo[j], hi[j]);
        size_t r0 = (size_t)(m0 + tm8 + 2 * p) * ldo + nc0 + tn8;
        size_t r1 = r0 + ldo;
        float4 v;
        v.x = lo[0] + bl[0]; v.y = lo[1] + bl[1]; v.z = lo[2] + bl[2]; v.w = lo[3] + bl[3];
        *(float4*)&Out[r0] = v;
        v.x = lo[4] + bl[4]; v.y = lo[5] + bl[5]; v.z = lo[6] + bl[6]; v.w = lo[7] + bl[7];
        *(float4*)&Out[r0 + 4] = v;
        v.x = hi[0] + bl[0]; v.y = hi[1] + bl[1]; v.z = hi[2] + bl[2]; v.w = hi[3] + bl[3];
        *(float4*)&Out[r1] = v;
        v.x = hi[4] + bl[4]; v.y = hi[5] + bl[5]; v.z = hi[6] + bl[6]; v.w = hi[7] + bl[7];
        *(float4*)&Out[r1 + 4] = v;
    }
}

// =============================================================================
// Kernel 2: persistent recurrence. 128 blocks x 16 batches, 256 threads.
// Weights (Wg_h 128KB + Wc_h 64KB) resident in SMEM for all 200 steps.
// h stored transposed hT[k][b] so batch-pairs load as f32x2 directly.
// =============================================================================
#define BPB      16
#define HSTRIDE  20    // padded [k][b] stride (floats), 16B-aligned, low-conflict
#define USTRIDE  132

#define SMEM_REC_FLOATS (128*256 + 128*128 + 128*HSTRIDE + 128*HSTRIDE + BPB*USTRIDE)
#define SMEM_REC_BYTES  (SMEM_REC_FLOATS * 4)

__global__ void __launch_bounds__(256, 1) augru_recurrent(
    const float* __restrict__ Gx,      // [B,T,256]
    const float* __restrict__ Cx,      // [B,T,128]
    const float* __restrict__ att,     // [B,T]
    const int*   __restrict__ seqlen,  // [B]
    const float* __restrict__ Wg,      // [256,256] (h-part = rows 128..255)
    const float* __restrict__ Wc,      // [256,128] (h-part = rows 128..255)
    float* __restrict__ out)           // [B,T,128]
{
    extern __shared__ float sm[];
    float* Wgh = sm;                      // [128][256]
    float* Wch = Wgh + 128 * 256;         // [128][128]
    float* hT  = Wch + 128 * 128;         // [128][HSTRIDE] : hT[k*HSTRIDE + b]
    float* hrT = hT  + 128 * HSTRIDE;     // r*h, same layout
    float* uu  = hrT + 128 * HSTRIDE;     // [BPB][USTRIDE] : attention-scaled u

    const int tid = threadIdx.x;
    const int b0  = blockIdx.x * BPB;

    // load recurrent weights once (contiguous h-part blocks)
    {
        const float4* s = (const float4*)(Wg + 128 * 256);
        float4* d = (float4*)Wgh;
        for (int i = tid; i < 128 * 256 / 4; i += 256) d[i] = s[i];
        const float4* s2 = (const float4*)(Wc + 128 * 128);
        float4* d2 = (float4*)Wch;
        for (int i = tid; i < 128 * 128 / 4; i += 256) d2[i] = s2[i];
    }
    for (int i = tid; i < 128 * HSTRIDE; i += 256) hT[i] = 0.0f;

    // lane mapping: bg fastest so warps dedup weight LDS via broadcast
    const int bg = tid & 3;        // 4 batch-groups of 4 batches
    const int cg = tid >> 2;       // 0..63
    const int bb = bg * 4;         // local batch base
    const int c0 = cg * 4;         // gate column base (4 cols)
    const int j0 = cg * 2;         // candidate column base (2 cols)

    int sl[4];
#pragma unroll
    for (int i = 0; i < 4; i++) sl[i] = seqlen[b0 + bb + i];

    for (int t = 0; t < T_; t++) {
        __syncthreads();   // hT from previous step visible

        // ---- gate GEMM: Gh[b][c] = h @ Wg_h, pairs over batch ----
        ull acc[2][4];
#pragma unroll
        for (int p = 0; p < 2; p++)
#pragma unroll
            for (int j = 0; j < 4; j++) acc[p][j] = 0ull;

#pragma unroll 16
        for (int k = 0; k < 128; k++) {
            ulonglong2 hv = *(const ulonglong2*)&hT[k * HSTRIDE + bb];
            float4 wv = *(const float4*)&Wgh[k * 256 + c0];
            ull w0 = pack2(wv.x, wv.x), w1 = pack2(wv.y, wv.y);
            ull w2 = pack2(wv.z, wv.z), w3 = pack2(wv.w, wv.w);
            fma2(acc[0][0], hv.x, w0); fma2(acc[1][0], hv.y, w0);
            fma2(acc[0][1], hv.x, w1); fma2(acc[1][1], hv.y, w1);
            fma2(acc[0][2], hv.x, w2); fma2(acc[1][2], hv.y, w2);
            fma2(acc[0][3], hv.x, w3); fma2(acc[1][3], hv.y, w3);
        }
        float gih[4][4];
#pragma unroll
        for (int p = 0; p < 2; p++)
#pragma unroll
            for (int j = 0; j < 4; j++)
                unpack2(acc[p][j], gih[2 * p][j], gih[2 * p + 1][j]);

        // ---- epilogue: +Gx, sigmoid; r -> hrT, u -> a*u in uu ----
        if (c0 < 128) {
#pragma unroll
            for (int i = 0; i < 4; i++) {
                int b = b0 + bb + i;
                float4 gx = *(const float4*)&Gx[((size_t)b * T_ + t) * 256 + c0];
                float r0 = sigmoidf_(gih[i][0] + gx.x);
                float r1 = sigmoidf_(gih[i][1] + gx.y);
                float r2 = sigmoidf_(gih[i][2] + gx.z);
                float r3 = sigmoidf_(gih[i][3] + gx.w);
                hrT[(c0 + 0) * HSTRIDE + bb + i] = r0 * hT[(c0 + 0) * HSTRIDE + bb + i];
                hrT[(c0 + 1) * HSTRIDE + bb + i] = r1 * hT[(c0 + 1) * HSTRIDE + bb + i];
                hrT[(c0 + 2) * HSTRIDE + bb + i] = r2 * hT[(c0 + 2) * HSTRIDE + bb + i];
                hrT[(c0 + 3) * HSTRIDE + bb + i] = r3 * hT[(c0 + 3) * HSTRIDE + bb + i];
            }
        } else {
            int cu = c0 - 128;
#pragma unroll
            for (int i = 0; i < 4; i++) {
                int b = b0 + bb + i;
                float at = att[(size_t)b * T_ + t];
                float4 gx = *(const float4*)&Gx[((size_t)b * T_ + t) * 256 + c0];
                uu[(bb + i) * USTRIDE + cu + 0] = at * sigmoidf_(gih[i][0] + gx.x);
                uu[(bb + i) * USTRIDE + cu + 1] = at * sigmoidf_(gih[i][1] + gx.y);
                uu[(bb + i) * USTRIDE + cu + 2] = at * sigmoidf_(gih[i][2] + gx.z);
                uu[(bb + i) * USTRIDE + cu + 3] = at * sigmoidf_(gih[i][3] + gx.w);
            }
        }
        __syncthreads();   // hrT, uu ready

        // ---- candidate GEMM: Ch[b][j] = (r*h) @ Wc_h ----
        ull a2[2][2];
        a2[0][0] = a2[0][1] = a2[1][0] = a2[1][1] = 0ull;
#pragma unroll 16
        for (int k = 0; k < 128; k++) {
            ulonglong2 hv = *(const ulonglong2*)&hrT[k * HSTRIDE + bb];
            float2 wv = *(const float2*)&Wch[k * 128 + j0];
            ull w0 = pack2(wv.x, wv.x), w1 = pack2(wv.y, wv.y);
            fma2(a2[0][0], hv.x, w0); fma2(a2[1][0], hv.y, w0);
            fma2(a2[0][1], hv.x, w1); fma2(a2[1][1], hv.y, w1);
        }
        float cc[4][2];
        unpack2(a2[0][0], cc[0][0], cc[1][0]);
        unpack2(a2[1][0], cc[2][0], cc[3][0]);
        unpack2(a2[0][1], cc[0][1], cc[1][1]);
        unpack2(a2[1][1], cc[2][1], cc[3][1]);

        // ---- update + masked output (exclusive (b,j) ownership) ----
#pragma unroll
        for (int i = 0; i < 4; i++) {
            int b = b0 + bb + i;
            float2 cx = *(const float2*)&Cx[((size_t)b * T_ + t) * 128 + j0];
            bool valid = (t < sl[i]);
            float c0v = tanhf(cc[i][0] + cx.x);
            float c1v = tanhf(cc[i][1] + cx.y);
            float u0 = uu[(bb + i) * USTRIDE + j0 + 0];
            float u1 = uu[(bb + i) * USTRIDE + j0 + 1];
            float h0 = hT[(j0 + 0) * HSTRIDE + bb + i];
            float h1 = hT[(j0 + 1) * HSTRIDE + bb + i];
            float hn0 = (1.0f - u0) * h0 + u0 * c0v;
            float hn1 = (1.0f - u1) * h1 + u1 * c1v;
            float* op = &out[((size_t)b * T_ + t) * 128 + j0];
            op[0] = valid ? hn0 : 0.0f;
            op[1] = valid ? hn1 : 0.0f;
            hT[(j0 + 0) * HSTRIDE + bb + i] = valid ? hn0 : h0;
            hT[(j0 + 1) * HSTRIDE + bb + i] = valid ? hn1 : h1;
        }
        // loop-top __syncthreads() orders hT writes vs next-step reads
    }
}

// =============================================================================
extern "C" void kernel_launch(void* const* d_in, const int* in_sizes, int n_in,
                              void* d_out, int out_size)
{
    (void)in_sizes; (void)n_in; (void)out_size;
    const float* X      = (const float*)d_in[0];  // inputs [B,T,D]
    const float* att    = (const float*)d_in[1];  // att_scores [B,T]
    const int*   seqlen = (const int*)  d_in[2];  // seq_len [B]
    const float* Wg     = (const float*)d_in[3];  // [256,256]
    const float* bg     = (const float*)d_in[4];  // [256]
    const float* Wc     = (const float*)d_in[5];  // [256,128]
    const float* bc     = (const float*)d_in[6];  // [128]
    float* out          = (float*)d_out;

    float *Gx, *Cx;
    cudaGetSymbolAddress((void**)&Gx, g_Gx);
    cudaGetSymbolAddress((void**)&Cx, g_Cx);

    dim3 gpre(M_ / 128, 3);
    augru_precompute<<<gpre, 256>>>(X, Wg, bg, Wc, bc, Gx, Cx);

    cudaFuncSetAttribute(augru_recurrent,
                         cudaFuncAttributeMaxDynamicSharedMemorySize, SMEM_REC_BYTES);
    augru_recurrent<<<B_ / BPB, 256, SMEM_REC_BYTES>>>(Gx, Cx, att, seqlen, Wg, Wc, out);
}

// round 3
// speedup vs baseline: 1.1340x; 1.1340x over previous
#include <cuda_runtime.h>

#define B_   2048
#define T_   200
#define D_   128
#define H_   128
#define M_   (B_ * T_)          // 409600 rows

typedef unsigned long long ull;

// ---------------- scratch (static device arrays; no allocation) ----------------
__device__ float g_Gx[(size_t)M_ * 256];   // x-part of gate pre-activations (+bg)
__device__ float g_Cx[(size_t)M_ * 128];   // x-part of candidate pre-activations (+bc)
__device__ int   g_perm[B_];               // batch index sorted by seq_len descending
__device__ int   g_sls[B_];                // sorted seq_len values (descending)

// ---------------- f32x2 helpers (sm_103a packed FMA: 2x FFMA throughput) -------
__device__ __forceinline__ ull pack2(float x, float y) {
    ull r; asm("mov.b64 %0, {%1, %2};" : "=l"(r) : "f"(x), "f"(y)); return r;
}
__device__ __forceinline__ void unpack2(ull v, float& x, float& y) {
    asm("mov.b64 {%0, %1}, %2;" : "=f"(x), "=f"(y) : "l"(v));
}
__device__ __forceinline__ void fma2(ull& d, ull a, ull b) {
    asm("fma.rn.f32x2 %0, %1, %2, %0;" : "+l"(d) : "l"(a), "l"(b));
}
__device__ __forceinline__ float sigmoidf_(float x) {
    return 1.0f / (1.0f + __expf(-x));
}

// =============================================================================
// Kernel 0: deterministic counting sort of batches by seq_len, DESCENDING.
// Thread s claims the contiguous output slots of all batches with sl==s
// (offset = #batches with sl > s), filling them in ascending batch order.
// =============================================================================
__global__ void __launch_bounds__(256) augru_sort(const int* __restrict__ seqlen,
                                                  int* __restrict__ perm,
                                                  int* __restrict__ sls)
{
    __shared__ int sl[B_];
    const int tid = threadIdx.x;
    for (int i = tid; i < B_; i += 256) sl[i] = seqlen[i];
    __syncthreads();
    for (int s = tid; s < T_; s += 256) {
        int pos = 0;
        for (int b = 0; b < B_; b++) pos += (sl[b] > s);
        for (int b = 0; b < B_; b++) {
            if (sl[b] == s) { perm[pos] = b; sls[pos] = s; pos++; }
        }
    }
}

// =============================================================================
// Kernel 1: precompute GEMM  [M,128] @ [128,384] -> Gx[M,256] (+bg), Cx[M,128] (+bc)
// Tile: 128(M) x 128(N), KC=16, 256 threads, thread tile 8x8 via f32x2 pairs.
// Tiles whose rows are ALL t >= seq_len[b] are skipped (outputs never read).
// =============================================================================
#define ASTRIDE 132

__global__ void __launch_bounds__(256) augru_precompute(
    const float* __restrict__ X,    // [M,128]
    const float* __restrict__ Wg,   // [256,256]
    const float* __restrict__ bg,   // [256]
    const float* __restrict__ Wc,   // [256,128]
    const float* __restrict__ bc,   // [128]
    const int*   __restrict__ seqlen,
    float* __restrict__ Gx,         // [M,256]
    float* __restrict__ Cx)         // [M,128]
{
    const int m0 = blockIdx.x * 128;

    // ---- early skip: tile rows m0..m0+127 all masked? ----
    {
        int b1 = m0 / T_;
        int t1 = m0 - b1 * T_;
        bool any = (t1 < seqlen[b1]);
        int b2 = (m0 + 127) / T_;
        if (b2 != b1) any = any || (seqlen[b2] > 0);
        if (!any) return;
    }

    __shared__ float As[16][ASTRIDE];  // transposed A tile: As[k][m]
    __shared__ float Bs[16][128];      // Bs[k][n]

    const int tid = threadIdx.x;
    const int nt  = blockIdx.y;        // 0,1 -> Wg cols; 2 -> Wc

    const float* W; int ldw, nc0; const float* bias; float* Out; int ldo;
    if (nt < 2) { W = Wg; ldw = 256; nc0 = nt * 128; bias = bg; Out = Gx; ldo = 256; }
    else        { W = Wc; ldw = 128; nc0 = 0;        bias = bc; Out = Cx; ldo = 128; }

    const int w    = tid >> 5, lane = tid & 31;
    const int wm   = w & 3,    wn   = w >> 2;
    const int lm   = lane & 3, ln   = lane >> 2;
    const int tm8  = wm * 32 + lm * 8;
    const int tn8  = wn * 64 + ln * 8;

    ull acc[4][8];
#pragma unroll
    for (int p = 0; p < 4; p++)
#pragma unroll
        for (int j = 0; j < 8; j++) acc[p][j] = 0ull;

    for (int k0 = 0; k0 < 128; k0 += 16) {
#pragma unroll
        for (int q = 0; q < 2; q++) {
            int idx = tid + q * 256;
            int m = idx >> 2, c = idx & 3;
            float4 v = *(const float4*)&X[(size_t)(m0 + m) * 128 + k0 + c * 4];
            As[c * 4 + 0][m] = v.x; As[c * 4 + 1][m] = v.y;
            As[c * 4 + 2][m] = v.z; As[c * 4 + 3][m] = v.w;
        }
#pragma unroll
        for (int q = 0; q < 2; q++) {
            int idx = tid + q * 256;
            int k = idx >> 5, n = (idx & 31) * 4;
            *(float4*)&Bs[k][n] = *(const float4*)&W[(size_t)(k0 + k) * ldw + nc0 + n];
        }
        __syncthreads();

#pragma unroll
        for (int k = 0; k < 16; k++) {
            ulonglong2 a01 = *(const ulonglong2*)&As[k][tm8];
            ulonglong2 a23 = *(const ulonglong2*)&As[k][tm8 + 4];
            float4 b0 = *(const float4*)&Bs[k][tn8];
            float4 b1 = *(const float4*)&Bs[k][tn8 + 4];
            ull ap[4] = {a01.x, a01.y, a23.x, a23.y};
            ull bd[8];
            bd[0] = pack2(b0.x, b0.x); bd[1] = pack2(b0.y, b0.y);
            bd[2] = pack2(b0.z, b0.z); bd[3] = pack2(b0.w, b0.w);
            bd[4] = pack2(b1.x, b1.x); bd[5] = pack2(b1.y, b1.y);
            bd[6] = pack2(b1.z, b1.z); bd[7] = pack2(b1.w, b1.w);
#pragma unroll
            for (int p = 0; p < 4; p++)
#pragma unroll
                for (int j = 0; j < 8; j++) fma2(acc[p][j], ap[p], bd[j]);
        }
        __syncthreads();
    }

    float bl[8];
#pragma unroll
    for (int j = 0; j < 8; j++) bl[j] = bias[nc0 + tn8 + j];

#pragma unroll
    for (int p = 0; p < 4; p++) {
        float lo[8], hi[8];
#pragma unroll
        for (int j = 0; j < 8; j++) unpack2(acc[p][j], lo[j], hi[j]);
        size_t r0 = (size_t)(m0 + tm8 + 2 * p) * ldo + nc0 + tn8;
        size_t r1 = r0 + ldo;
        float4 v;
        v.x = lo[0] + bl[0]; v.y = lo[1] + bl[1]; v.z = lo[2] + bl[2]; v.w = lo[3] + bl[3];
        *(float4*)&Out[r0] = v;
        v.x = lo[4] + bl[4]; v.y = lo[5] + bl[5]; v.z = lo[6] + bl[6]; v.w = lo[7] + bl[7];
        *(float4*)&Out[r0 + 4] = v;
        v.x = hi[0] + bl[0]; v.y = hi[1] + bl[1]; v.z = hi[2] + bl[2]; v.w = hi[3] + bl[3];
        *(float4*)&Out[r1] = v;
        v.x = hi[4] + bl[4]; v.y = hi[5] + bl[5]; v.z = hi[6] + bl[6]; v.w = hi[7] + bl[7];
        *(float4*)&Out[r1 + 4] = v;
    }
}

// =============================================================================
// Kernel 2: persistent recurrence. BPB=8 sorted batches per block, 256 blocks,
// 512 threads (16 warps). Weights transposed [col][k] in SMEM, h batch-major.
// k-parity f32x2 accumulation: no splat movs at all.
// Block runs only t < max(seq_len of its 8 batches), then zero-fills the tail.
// =============================================================================
#define BPB      8
#define THR      512
#define KS       132   // padded k-stride (floats): 16B aligned, 4-bank step per row

#define SMEM_REC_FLOATS (256*KS + 128*KS + 3*BPB*KS)
#define SMEM_REC_BYTES  (SMEM_REC_FLOATS * 4)

__global__ void __launch_bounds__(THR, 1) augru_recurrent(
    const float* __restrict__ Gx,      // [B,T,256]
    const float* __restrict__ Cx,      // [B,T,128]
    const float* __restrict__ att,     // [B,T]
    const int*   __restrict__ perm,    // [B] sorted desc by seq_len
    const int*   __restrict__ sls,     // [B] sorted seq_len
    const float* __restrict__ Wg,      // [256,256] (h-part = rows 128..255)
    const float* __restrict__ Wc,      // [256,128] (h-part = rows 128..255)
    float* __restrict__ out)           // [B,T,128]
{
    extern __shared__ float sm[];
    float* WghT = sm;                   // [256][KS]  WghT[c][k] = Wg[128+k][c]
    float* WchT = WghT + 256 * KS;      // [128][KS]
    float* hB   = WchT + 128 * KS;      // [BPB][KS]  h, batch-major
    float* hrB  = hB   + BPB * KS;      // r*h
    float* uu   = hrB  + BPB * KS;      // att-scaled update gate

    const int tid = threadIdx.x;
    const int g0  = blockIdx.x * BPB;

    // ---- load + transpose recurrent weights (once) ----
    for (int idx = tid; idx < 128 * 64; idx += THR) {
        int k = idx >> 6, c4 = (idx & 63) << 2;
        float4 v = *(const float4*)&Wg[(size_t)(128 + k) * 256 + c4];
        WghT[(c4 + 0) * KS + k] = v.x; WghT[(c4 + 1) * KS + k] = v.y;
        WghT[(c4 + 2) * KS + k] = v.z; WghT[(c4 + 3) * KS + k] = v.w;
    }
    for (int idx = tid; idx < 128 * 32; idx += THR) {
        int k = idx >> 5, c4 = (idx & 31) << 2;
        float4 v = *(const float4*)&Wc[(size_t)(128 + k) * 128 + c4];
        WchT[(c4 + 0) * KS + k] = v.x; WchT[(c4 + 1) * KS + k] = v.y;
        WchT[(c4 + 2) * KS + k] = v.z; WchT[(c4 + 3) * KS + k] = v.w;
    }
    for (int i = tid; i < 3 * BPB * KS; i += THR) hB[i] = 0.0f;

    // lane mapping: bq fastest (weight LDS dedups via broadcast, 8 distinct cq
    // per warp at 4-bank steps -> conflict-free). Each thread owns 2 batches and
    // cols {cq, cq+128} for the gate (one reset + one update col), col cq for
    // the candidate.
    const int bq = tid & 3;
    const int cq = tid >> 2;           // 0..127
    const int bb = bq * 2;

    int pb[2], sl[2];
    pb[0] = perm[g0 + bb];     pb[1] = perm[g0 + bb + 1];
    sl[0] = sls[g0 + bb];      sl[1] = sls[g0 + bb + 1];
    const int maxsl = sls[g0];         // descending order -> first is block max

    const float* hp0 = hB  + (size_t)bb * KS;
    const float* hp1 = hB  + (size_t)(bb + 1) * KS;
    const float* rp0 = hrB + (size_t)bb * KS;
    const float* rp1 = hrB + (size_t)(bb + 1) * KS;
    const float* wr  = WghT + (size_t)cq * KS;          // reset col
    const float* wu  = WghT + (size_t)(cq + 128) * KS;  // update col
    const float* wc  = WchT + (size_t)cq * KS;          // candidate col

    __syncthreads();

    for (int t = 0; t < maxsl; t++) {
        // ---- gate GEMM (k-parity pairs, no splats) ----
        ull a0r = 0, a0u = 0, a1r = 0, a1u = 0;
#pragma unroll 8
        for (int k = 0; k < 128; k += 4) {
            ulonglong2 h0 = *(const ulonglong2*)&hp0[k];
            ulonglong2 h1 = *(const ulonglong2*)&hp1[k];
            ulonglong2 w0 = *(const ulonglong2*)&wr[k];
            ulonglong2 w1 = *(const ulonglong2*)&wu[k];
            fma2(a0r, h0.x, w0.x); fma2(a0r, h0.y, w0.y);
            fma2(a0u, h0.x, w1.x); fma2(a0u, h0.y, w1.y);
            fma2(a1r, h1.x, w0.x); fma2(a1r, h1.y, w0.y);
            fma2(a1u, h1.x, w1.x); fma2(a1u, h1.y, w1.y);
        }
        float lo, hi, g0r, g0u, g1r, g1u;
        unpack2(a0r, lo, hi); g0r = lo + hi;
        unpack2(a0u, lo, hi); g0u = lo + hi;
        unpack2(a1r, lo, hi); g1r = lo + hi;
        unpack2(a1u, lo, hi); g1u = lo + hi;

        // ---- epilogue: sigmoid; r -> hrB, a*u -> uu ----
        const size_t row0 = (size_t)pb[0] * T_ + t;
        const size_t row1 = (size_t)pb[1] * T_ + t;
        {
            float r0 = sigmoidf_(g0r + Gx[row0 * 256 + cq]);
            float r1 = sigmoidf_(g1r + Gx[row1 * 256 + cq]);
            hrB[bb * KS + cq]       = r0 * hp0[cq];
            hrB[(bb + 1) * KS + cq] = r1 * hp1[cq];
            float at0 = att[row0], at1 = att[row1];
            uu[bb * KS + cq]       = at0 * sigmoidf_(g0u + Gx[row0 * 256 + 128 + cq]);
            uu[(bb + 1) * KS + cq] = at1 * sigmoidf_(g1u + Gx[row1 * 256 + 128 + cq]);
        }
        __syncthreads();   // hrB, uu ready

        // ---- candidate GEMM ----
        ull c0a = 0, c1a = 0;
#pragma unroll 8
        for (int k = 0; k < 128; k += 4) {
            ulonglong2 h0 = *(const ulonglong2*)&rp0[k];
            ulonglong2 h1 = *(const ulonglong2*)&rp1[k];
            ulonglong2 w  = *(const ulonglong2*)&wc[k];
            fma2(c0a, h0.x, w.x); fma2(c0a, h0.y, w.y);
            fma2(c1a, h1.x, w.x); fma2(c1a, h1.y, w.y);
        }
        float cc0, cc1;
        unpack2(c0a, lo, hi); cc0 = lo + hi;
        unpack2(c1a, lo, hi); cc1 = lo + hi;

        // ---- update + masked output (exclusive (b,cq) ownership) ----
        {
            float cv0 = tanhf(cc0 + Cx[row0 * 128 + cq]);
            float cv1 = tanhf(cc1 + Cx[row1 * 128 + cq]);
            float u0 = uu[bb * KS + cq],       u1 = uu[(bb + 1) * KS + cq];
            float h0 = hB[bb * KS + cq],       h1 = hB[(bb + 1) * KS + cq];
            float hn0 = (1.0f - u0) * h0 + u0 * cv0;
            float hn1 = (1.0f - u1) * h1 + u1 * cv1;
            bool v0 = (t < sl[0]), v1 = (t < sl[1]);
            out[row0 * 128 + cq] = v0 ? hn0 : 0.0f;
            out[row1 * 128 + cq] = v1 ? hn1 : 0.0f;
            hB[bb * KS + cq]       = v0 ? hn0 : h0;
            hB[(bb + 1) * KS + cq] = v1 ? hn1 : h1;
        }
        __syncthreads();   // hB stable before next gate reads
    }

    // ---- zero tail: t in [maxsl, T) for all 8 batches ----
    for (int idx = tid; idx < (T_ - maxsl) * BPB * 32; idx += THR) {
        int t  = maxsl + idx / (BPB * 32);
        int r  = idx % (BPB * 32);
        int i  = r >> 5;
        int j4 = (r & 31) << 2;
        int b  = perm[g0 + i];
        *(float4*)&out[((size_t)b * T_ + t) * 128 + j4] = make_float4(0.f, 0.f, 0.f, 0.f);
    }
}

// =============================================================================
extern "C" void kernel_launch(void* const* d_in, const int* in_sizes, int n_in,
                              void* d_out, int out_size)
{
    (void)in_sizes; (void)n_in; (void)out_size;
    const float* X      = (const float*)d_in[0];  // inputs [B,T,D]
    const float* att    = (const float*)d_in[1];  // att_scores [B,T]
    const int*   seqlen = (const int*)  d_in[2];  // seq_len [B]
    const float* Wg     = (const float*)d_in[3];  // [256,256]
    const float* bg     = (const float*)d_in[4];  // [256]
    const float* Wc     = (const float*)d_in[5];  // [256,128]
    const float* bc     = (const float*)d_in[6];  // [128]
    float* out          = (float*)d_out;

    float *Gx, *Cx; int *perm, *sls;
    cudaGetSymbolAddress((void**)&Gx,   g_Gx);
    cudaGetSymbolAddress((void**)&Cx,   g_Cx);
    cudaGetSymbolAddress((void**)&perm, g_perm);
    cudaGetSymbolAddress((void**)&sls,  g_sls);

    augru_sort<<<1, 256>>>(seqlen, perm, sls);

    dim3 gpre(M_ / 128, 3);
    augru_precompute<<<gpre, 256>>>(X, Wg, bg, Wc, bc, seqlen, Gx, Cx);

    cudaFuncSetAttribute(augru_recurrent,
                         cudaFuncAttributeMaxDynamicSharedMemorySize, SMEM_REC_BYTES);
    augru_recurrent<<<B_ / BPB, THR, SMEM_REC_BYTES>>>(Gx, Cx, att, perm, sls, Wg, Wc, out);
}

// round 4
// speedup vs baseline: 1.4349x; 1.2654x over previous
#include <cuda_runtime.h>

#define B_   2048
#define T_   200
#define D_   128
#define H_   128
#define M_   (B_ * T_)          // 409600 rows

typedef unsigned long long ull;

// ---------------- scratch (static device arrays; no allocation) ----------------
__device__ float g_Gx[(size_t)M_ * 256];   // x-part of gate pre-activations (+bg)
__device__ float g_Cx[(size_t)M_ * 128];   // x-part of candidate pre-activations (+bc)
__device__ int   g_perm[B_];               // batch index sorted by seq_len descending
__device__ int   g_sls[B_];                // sorted seq_len values (descending)

// ---------------- f32x2 helpers (sm_103a packed FMA: 2x FFMA throughput) -------
__device__ __forceinline__ ull pack2(float x, float y) {
    ull r; asm("mov.b64 %0, {%1, %2};" : "=l"(r) : "f"(x), "f"(y)); return r;
}
__device__ __forceinline__ void unpack2(ull v, float& x, float& y) {
    asm("mov.b64 {%0, %1}, %2;" : "=f"(x), "=f"(y) : "l"(v));
}
__device__ __forceinline__ void fma2(ull& d, ull a, ull b) {
    asm("fma.rn.f32x2 %0, %1, %2, %0;" : "+l"(d) : "l"(a), "l"(b));
}
// MUFU-only sigmoid/tanh: ex2.approx + rcp.approx (~1e-6 rel err, no branches,
// no fp32 division sequence, no accurate-tanhf blob on the barrier critical path)
__device__ __forceinline__ float sigmoid_fast(float x) {
    float e;
    asm("ex2.approx.f32 %0, %1;" : "=f"(e) : "f"(-1.4426950408889634f * x));
    float r;
    asm("rcp.approx.f32 %0, %1;" : "=f"(r) : "f"(1.0f + e));
    return r;
}
__device__ __forceinline__ float tanh_fast(float x) {
    return fmaf(2.0f, sigmoid_fast(2.0f * x), -1.0f);
}

// =============================================================================
// Kernel 0: parallel deterministic sort of batches by seq_len, DESCENDING.
// One thread per batch computes its rank = #(sl[j] > sl[b]) + #(tie && j < b).
// 8 blocks x 256 threads; each block caches sl[] in smem (broadcast-friendly).
// =============================================================================
__global__ void __launch_bounds__(256) augru_sort(const int* __restrict__ seqlen,
                                                  int* __restrict__ perm,
                                                  int* __restrict__ sls)
{
    __shared__ int sl[B_];
    const int tid = threadIdx.x;
    for (int i = tid; i < B_; i += 256) sl[i] = seqlen[i];
    __syncthreads();
    const int b = blockIdx.x * 256 + tid;
    const int v = sl[b];
    int pos = 0;
#pragma unroll 8
    for (int j = 0; j < B_; j++) {
        int u = sl[j];
        pos += (u > v) || (u == v && j < b);
    }
    perm[pos] = b;
    sls[pos]  = v;
}

// =============================================================================
// Kernel 1: precompute GEMM  [M,128] @ [128,384] -> Gx[M,256] (+bg), Cx[M,128] (+bc)
// Tile: 128(M) x 128(N), KC=16, 256 threads, thread tile 8x8 via f32x2 pairs.
// Tiles whose rows are ALL t >= seq_len[b] are skipped (outputs never read).
// =============================================================================
#define ASTRIDE 132

__global__ void __launch_bounds__(256) augru_precompute(
    const float* __restrict__ X,    // [M,128]
    const float* __restrict__ Wg,   // [256,256]
    const float* __restrict__ bg,   // [256]
    const float* __restrict__ Wc,   // [256,128]
    const float* __restrict__ bc,   // [128]
    const int*   __restrict__ seqlen,
    float* __restrict__ Gx,         // [M,256]
    float* __restrict__ Cx)         // [M,128]
{
    const int m0 = blockIdx.x * 128;

    // ---- early skip: tile rows m0..m0+127 all masked? ----
    {
        int b1 = m0 / T_;
        int t1 = m0 - b1 * T_;
        bool any = (t1 < seqlen[b1]);
        int b2 = (m0 + 127) / T_;
        if (b2 != b1) any = any || (seqlen[b2] > 0);
        if (!any) return;
    }

    __shared__ float As[16][ASTRIDE];  // transposed A tile: As[k][m]
    __shared__ float Bs[16][128];      // Bs[k][n]

    const int tid = threadIdx.x;
    const int nt  = blockIdx.y;        // 0,1 -> Wg cols; 2 -> Wc

    const float* W; int ldw, nc0; const float* bias; float* Out; int ldo;
    if (nt < 2) { W = Wg; ldw = 256; nc0 = nt * 128; bias = bg; Out = Gx; ldo = 256; }
    else        { W = Wc; ldw = 128; nc0 = 0;        bias = bc; Out = Cx; ldo = 128; }

    const int w    = tid >> 5, lane = tid & 31;
    const int wm   = w & 3,    wn   = w >> 2;
    const int lm   = lane & 3, ln   = lane >> 2;
    const int tm8  = wm * 32 + lm * 8;
    const int tn8  = wn * 64 + ln * 8;

    ull acc[4][8];
#pragma unroll
    for (int p = 0; p < 4; p++)
#pragma unroll
        for (int j = 0; j < 8; j++) acc[p][j] = 0ull;

    for (int k0 = 0; k0 < 128; k0 += 16) {
#pragma unroll
        for (int q = 0; q < 2; q++) {
            int idx = tid + q * 256;
            int m = idx >> 2, c = idx & 3;
            float4 v = *(const float4*)&X[(size_t)(m0 + m) * 128 + k0 + c * 4];
            As[c * 4 + 0][m] = v.x; As[c * 4 + 1][m] = v.y;
            As[c * 4 + 2][m] = v.z; As[c * 4 + 3][m] = v.w;
        }
#pragma unroll
        for (int q = 0; q < 2; q++) {
            int idx = tid + q * 256;
            int k = idx >> 5, n = (idx & 31) * 4;
            *(float4*)&Bs[k][n] = *(const float4*)&W[(size_t)(k0 + k) * ldw + nc0 + n];
        }
        __syncthreads();

#pragma unroll
        for (int k = 0; k < 16; k++) {
            ulonglong2 a01 = *(const ulonglong2*)&As[k][tm8];
            ulonglong2 a23 = *(const ulonglong2*)&As[k][tm8 + 4];
            float4 b0 = *(const float4*)&Bs[k][tn8];
            float4 b1 = *(const float4*)&Bs[k][tn8 + 4];
            ull ap[4] = {a01.x, a01.y, a23.x, a23.y};
            ull bd[8];
            bd[0] = pack2(b0.x, b0.x); bd[1] = pack2(b0.y, b0.y);
            bd[2] = pack2(b0.z, b0.z); bd[3] = pack2(b0.w, b0.w);
            bd[4] = pack2(b1.x, b1.x); bd[5] = pack2(b1.y, b1.y);
            bd[6] = pack2(b1.z, b1.z); bd[7] = pack2(b1.w, b1.w);
#pragma unroll
            for (int p = 0; p < 4; p++)
#pragma unroll
                for (int j = 0; j < 8; j++) fma2(acc[p][j], ap[p], bd[j]);
        }
        __syncthreads();
    }

    float bl[8];
#pragma unroll
    for (int j = 0; j < 8; j++) bl[j] = bias[nc0 + tn8 + j];

#pragma unroll
    for (int p = 0; p < 4; p++) {
        float lo[8], hi[8];
#pragma unroll
        for (int j = 0; j < 8; j++) unpack2(acc[p][j], lo[j], hi[j]);
        size_t r0 = (size_t)(m0 + tm8 + 2 * p) * ldo + nc0 + tn8;
        size_t r1 = r0 + ldo;
        float4 v;
        v.x = lo[0] + bl[0]; v.y = lo[1] + bl[1]; v.z = lo[2] + bl[2]; v.w = lo[3] + bl[3];
        *(float4*)&Out[r0] = v;
        v.x = lo[4] + bl[4]; v.y = lo[5] + bl[5]; v.z = lo[6] + bl[6]; v.w = lo[7] + bl[7];
        *(float4*)&Out[r0 + 4] = v;
        v.x = hi[0] + bl[0]; v.y = hi[1] + bl[1]; v.z = hi[2] + bl[2]; v.w = hi[3] + bl[3];
        *(float4*)&Out[r1] = v;
        v.x = hi[4] + bl[4]; v.y = hi[5] + bl[5]; v.z = hi[6] + bl[6]; v.w = hi[7] + bl[7];
        *(float4*)&Out[r1 + 4] = v;
    }
}

// =============================================================================
// Kernel 2: persistent recurrence. BPB=8 sorted batches per block, 256 blocks,
// 512 threads. Weights transposed [col][k] in SMEM, h batch-major, k-parity
// f32x2 accumulation. NEW: t+1 inputs (Gx/att/Cx) are register-prefetched one
// step ahead so DRAM latency overlaps the GEMM phase instead of sitting on the
// barrier-serialized critical path.
// =============================================================================
#define BPB      8
#define THR      512
#define KS       132   // padded k-stride (floats): 16B aligned, conflict-free

#define SMEM_REC_FLOATS (256*KS + 128*KS + 3*BPB*KS)
#define SMEM_REC_BYTES  (SMEM_REC_FLOATS * 4)

__global__ void __launch_bounds__(THR, 1) augru_recurrent(
    const float* __restrict__ Gx,      // [B,T,256]
    const float* __restrict__ Cx,      // [B,T,128]
    const float* __restrict__ att,     // [B,T]
    const int*   __restrict__ perm,    // [B] sorted desc by seq_len
    const int*   __restrict__ sls,     // [B] sorted seq_len
    const float* __restrict__ Wg,      // [256,256] (h-part = rows 128..255)
    const float* __restrict__ Wc,      // [256,128] (h-part = rows 128..255)
    float* __restrict__ out)           // [B,T,128]
{
    extern __shared__ float sm[];
    float* WghT = sm;                   // [256][KS]  WghT[c][k] = Wg[128+k][c]
    float* WchT = WghT + 256 * KS;      // [128][KS]
    float* hB   = WchT + 128 * KS;      // [BPB][KS]  h, batch-major
    float* hrB  = hB   + BPB * KS;      // r*h
    float* uu   = hrB  + BPB * KS;      // att-scaled update gate

    const int tid = threadIdx.x;
    const int g0  = blockIdx.x * BPB;

    // ---- load + transpose recurrent weights (once) ----
    for (int idx = tid; idx < 128 * 64; idx += THR) {
        int k = idx >> 6, c4 = (idx & 63) << 2;
        float4 v = *(const float4*)&Wg[(size_t)(128 + k) * 256 + c4];
        WghT[(c4 + 0) * KS + k] = v.x; WghT[(c4 + 1) * KS + k] = v.y;
        WghT[(c4 + 2) * KS + k] = v.z; WghT[(c4 + 3) * KS + k] = v.w;
    }
    for (int idx = tid; idx < 128 * 32; idx += THR) {
        int k = idx >> 5, c4 = (idx & 31) << 2;
        float4 v = *(const float4*)&Wc[(size_t)(128 + k) * 128 + c4];
        WchT[(c4 + 0) * KS + k] = v.x; WchT[(c4 + 1) * KS + k] = v.y;
        WchT[(c4 + 2) * KS + k] = v.z; WchT[(c4 + 3) * KS + k] = v.w;
    }
    for (int i = tid; i < 3 * BPB * KS; i += THR) hB[i] = 0.0f;

    const int bq = tid & 3;
    const int cq = tid >> 2;           // 0..127
    const int bb = bq * 2;

    int pb[2], sl[2];
    pb[0] = perm[g0 + bb];     pb[1] = perm[g0 + bb + 1];
    sl[0] = sls[g0 + bb];      sl[1] = sls[g0 + bb + 1];
    const int maxsl = sls[g0];         // descending order -> first is block max

    const float* hp0 = hB  + (size_t)bb * KS;
    const float* hp1 = hB  + (size_t)(bb + 1) * KS;
    const float* rp0 = hrB + (size_t)bb * KS;
    const float* rp1 = hrB + (size_t)(bb + 1) * KS;
    const float* wr  = WghT + (size_t)cq * KS;          // reset col
    const float* wu  = WghT + (size_t)(cq + 128) * KS;  // update col
    const float* wc  = WchT + (size_t)cq * KS;          // candidate col

    const size_t rb0 = (size_t)pb[0] * T_;   // row base (time-contiguous)
    const size_t rb1 = (size_t)pb[1] * T_;

    // ---- prefetch registers for step t (loaded one step ahead) ----
    float pgx0r = 0, pgx0u = 0, pgx1r = 0, pgx1u = 0;
    float pat0 = 0, pat1 = 0, pcx0 = 0, pcx1 = 0;
    if (maxsl > 0) {
        pgx0r = Gx[rb0 * 256 + cq];        pgx0u = Gx[rb0 * 256 + 128 + cq];
        pgx1r = Gx[rb1 * 256 + cq];        pgx1u = Gx[rb1 * 256 + 128 + cq];
        pat0  = att[rb0];                  pat1  = att[rb1];
        pcx0  = Cx[rb0 * 128 + cq];        pcx1  = Cx[rb1 * 128 + cq];
    }

    __syncthreads();

    for (int t = 0; t < maxsl; t++) {
        // consume this step's prefetched values
        const float gx0r = pgx0r, gx0u = pgx0u, gx1r = pgx1r, gx1u = pgx1u;
        const float at0 = pat0, at1 = pat1, cx0 = pcx0, cx1 = pcx1;

        // issue t+1 prefetch NOW — overlaps with the gate GEMM below
        if (t + 1 < maxsl) {
            const size_t n0 = (rb0 + t + 1), n1 = (rb1 + t + 1);
            pgx0r = Gx[n0 * 256 + cq];     pgx0u = Gx[n0 * 256 + 128 + cq];
            pgx1r = Gx[n1 * 256 + cq];     pgx1u = Gx[n1 * 256 + 128 + cq];
            pat0  = att[n0];               pat1  = att[n1];
            pcx0  = Cx[n0 * 128 + cq];     pcx1  = Cx[n1 * 128 + cq];
        }

        // ---- gate GEMM (k-parity f32x2 pairs, no splats) ----
        ull a0r = 0, a0u = 0, a1r = 0, a1u = 0;
#pragma unroll 8
        for (int k = 0; k < 128; k += 4) {
            ulonglong2 h0 = *(const ulonglong2*)&hp0[k];
            ulonglong2 h1 = *(const ulonglong2*)&hp1[k];
            ulonglong2 w0 = *(const ulonglong2*)&wr[k];
            ulonglong2 w1 = *(const ulonglong2*)&wu[k];
            fma2(a0r, h0.x, w0.x); fma2(a0r, h0.y, w0.y);
            fma2(a0u, h0.x, w1.x); fma2(a0u, h0.y, w1.y);
            fma2(a1r, h1.x, w0.x); fma2(a1r, h1.y, w0.y);
            fma2(a1u, h1.x, w1.x); fma2(a1u, h1.y, w1.y);
        }
        float lo, hi, g0r, g0u, g1r, g1u;
        unpack2(a0r, lo, hi); g0r = lo + hi;
        unpack2(a0u, lo, hi); g0u = lo + hi;
        unpack2(a1r, lo, hi); g1r = lo + hi;
        unpack2(a1u, lo, hi); g1u = lo + hi;

        // ---- epilogue: sigmoid (MUFU); r -> hrB, a*u -> uu ----
        {
            float r0 = sigmoid_fast(g0r + gx0r);
            float r1 = sigmoid_fast(g1r + gx1r);
            hrB[bb * KS + cq]       = r0 * hp0[cq];
            hrB[(bb + 1) * KS + cq] = r1 * hp1[cq];
            uu[bb * KS + cq]        = at0 * sigmoid_fast(g0u + gx0u);
            uu[(bb + 1) * KS + cq]  = at1 * sigmoid_fast(g1u + gx1u);
        }
        __syncthreads();   // hrB, uu ready

        // ---- candidate GEMM ----
        ull c0a = 0, c1a = 0;
#pragma unroll 8
        for (int k = 0; k < 128; k += 4) {
            ulonglong2 h0 = *(const ulonglong2*)&rp0[k];
            ulonglong2 h1 = *(const ulonglong2*)&rp1[k];
            ulonglong2 w  = *(const ulonglong2*)&wc[k];
            fma2(c0a, h0.x, w.x); fma2(c0a, h0.y, w.y);
            fma2(c1a, h1.x, w.x); fma2(c1a, h1.y, w.y);
        }
        float cc0, cc1;
        unpack2(c0a, lo, hi); cc0 = lo + hi;
        unpack2(c1a, lo, hi); cc1 = lo + hi;

        // ---- update + masked output (exclusive (b,cq) ownership) ----
        {
            float cv0 = tanh_fast(cc0 + cx0);
            float cv1 = tanh_fast(cc1 + cx1);
            float u0 = uu[bb * KS + cq],       u1 = uu[(bb + 1) * KS + cq];
            float h0 = hB[bb * KS + cq],       h1 = hB[(bb + 1) * KS + cq];
            float hn0 = (1.0f - u0) * h0 + u0 * cv0;
            float hn1 = (1.0f - u1) * h1 + u1 * cv1;
            bool v0 = (t < sl[0]), v1 = (t < sl[1]);
            out[(rb0 + t) * 128 + cq] = v0 ? hn0 : 0.0f;
            out[(rb1 + t) * 128 + cq] = v1 ? hn1 : 0.0f;
            hB[bb * KS + cq]       = v0 ? hn0 : h0;
            hB[(bb + 1) * KS + cq] = v1 ? hn1 : h1;
        }
        __syncthreads();   // hB stable before next gate reads
    }

    // ---- zero tail: t in [maxsl, T) for all 8 batches ----
    for (int idx = tid; idx < (T_ - maxsl) * BPB * 32; idx += THR) {
        int t  = maxsl + idx / (BPB * 32);
        int r  = idx % (BPB * 32);
        int i  = r >> 5;
        int j4 = (r & 31) << 2;
        int b  = perm[g0 + i];
        *(float4*)&out[((size_t)b * T_ + t) * 128 + j4] = make_float4(0.f, 0.f, 0.f, 0.f);
    }
}

// =============================================================================
extern "C" void kernel_launch(void* const* d_in, const int* in_sizes, int n_in,
                              void* d_out, int out_size)
{
    (void)in_sizes; (void)n_in; (void)out_size;
    const float* X      = (const float*)d_in[0];  // inputs [B,T,D]
    const float* att    = (const float*)d_in[1];  // att_scores [B,T]
    const int*   seqlen = (const int*)  d_in[2];  // seq_len [B]
    const float* Wg     = (const float*)d_in[3];  // [256,256]
    const float* bg     = (const float*)d_in[4];  // [256]
    const float* Wc     = (const float*)d_in[5];  // [256,128]
    const float* bc     = (const float*)d_in[6];  // [128]
    float* out          = (float*)d_out;

    float *Gx, *Cx; int *perm, *sls;
    cudaGetSymbolAddress((void**)&Gx,   g_Gx);
    cudaGetSymbolAddress((void**)&Cx,   g_Cx);
    cudaGetSymbolAddress((void**)&perm, g_perm);
    cudaGetSymbolAddress((void**)&sls,  g_sls);

    augru_sort<<<B_ / 256, 256>>>(seqlen, perm, sls);

    dim3 gpre(M_ / 128, 3);
    augru_precompute<<<gpre, 256>>>(X, Wg, bg, Wc, bc, seqlen, Gx, Cx);

    cudaFuncSetAttribute(augru_recurrent,
                         cudaFuncAttributeMaxDynamicSharedMemorySize, SMEM_REC_BYTES);
    augru_recurrent<<<B_ / BPB, THR, SMEM_REC_BYTES>>>(Gx, Cx, att, perm, sls, Wg, Wc, out);
}

// round 6
// speedup vs baseline: 1.6707x; 1.1643x over previous
#include <cuda_runtime.h>
#include <cuda_bf16.h>
#include <cstdint>

#define B_   2048
#define T_   200
#define D_   128
#define H_   128
#define M_   (B_ * T_)          // 409600 rows

typedef unsigned long long ull;

// ---------------- scratch (static device arrays; no allocation) ----------------
__device__ float g_Gx[(size_t)M_ * 256];   // x-part of gate pre-activations (NO bias)
__device__ float g_Cx[(size_t)M_ * 128];   // x-part of candidate pre-activations (NO bias)
__device__ int   g_perm[B_];
__device__ int   g_sls[B_];
__device__ __align__(16) __nv_bfloat16 g_WThi[384 * 128];  // W^T hi: [n][k]
__device__ __align__(16) __nv_bfloat16 g_WTlo[384 * 128];  // W^T lo (residual)

// ---------------- f32x2 helpers -------------------------------------------------
__device__ __forceinline__ ull pack2(float x, float y) {
    ull r; asm("mov.b64 %0, {%1, %2};" : "=l"(r) : "f"(x), "f"(y)); return r;
}
__device__ __forceinline__ void unpack2(ull v, float& x, float& y) {
    asm("mov.b64 {%0, %1}, %2;" : "=f"(x), "=f"(y) : "l"(v));
}
__device__ __forceinline__ void fma2(ull& d, ull a, ull b) {
    asm("fma.rn.f32x2 %0, %1, %2, %0;" : "+l"(d) : "l"(a), "l"(b));
}
__device__ __forceinline__ float sigmoid_fast(float x) {
    float e;
    asm("ex2.approx.f32 %0, %1;" : "=f"(e) : "f"(-1.4426950408889634f * x));
    float r;
    asm("rcp.approx.f32 %0, %1;" : "=f"(r) : "f"(1.0f + e));
    return r;
}
__device__ __forceinline__ float tanh_fast(float x) {
    return fmaf(2.0f, sigmoid_fast(2.0f * x), -1.0f);
}

// ---------------- warp-level bf16 MMA (sm_80+ feature, legal on compute_103) ----
__device__ __forceinline__ void mma16816(float* c,
    uint32_t a0, uint32_t a1, uint32_t a2, uint32_t a3,
    uint32_t b0, uint32_t b1)
{
    asm volatile(
        "mma.sync.aligned.m16n8k16.row.col.f32.bf16.bf16.f32 "
        "{%0,%1,%2,%3}, {%4,%5,%6,%7}, {%8,%9}, {%0,%1,%2,%3};"
        : "+f"(c[0]), "+f"(c[1]), "+f"(c[2]), "+f"(c[3])
        : "r"(a0), "r"(a1), "r"(a2), "r"(a3), "r"(b0), "r"(b1));
}

// =============================================================================
// Kernel 0a: W transpose + bf16 hi/lo split. WT[n][k] = W[k][n].
// n: 0..255 -> Wg cols, 256..383 -> Wc cols. 12 blocks x 256 threads.
// =============================================================================
__global__ void __launch_bounds__(256) augru_wprep(
    const float* __restrict__ Wg, const float* __restrict__ Wc,
    __nv_bfloat16* __restrict__ WThi, __nv_bfloat16* __restrict__ WTlo)
{
    __shared__ float s[32][33];
    const int n0 = blockIdx.x * 32;
    const int tx = threadIdx.x & 31, ty = threadIdx.x >> 5;   // 32 x 8
    for (int k0 = 0; k0 < 128; k0 += 32) {
        for (int rr = 0; rr < 32; rr += 8) {
            int k = k0 + ty + rr, n = n0 + tx;
            s[ty + rr][tx] = (n0 < 256) ? Wg[(size_t)k * 256 + n]
                                        : Wc[(size_t)k * 128 + (n - 256)];
        }
        __syncthreads();
        for (int rr = 0; rr < 32; rr += 8) {
            int n = n0 + ty + rr, k = k0 + tx;
            float v = s[tx][ty + rr];
            __nv_bfloat16 hi = __float2bfloat16(v);
            float lo = v - __bfloat162float(hi);
            WThi[(size_t)n * 128 + k] = hi;
            WTlo[(size_t)n * 128 + k] = __float2bfloat16(lo);
        }
        __syncthreads();
    }
}

// =============================================================================
// Kernel 0b: parallel deterministic sort of batches by seq_len, DESCENDING.
// =============================================================================
__global__ void __launch_bounds__(256) augru_sort(const int* __restrict__ seqlen,
                                                  int* __restrict__ perm,
                                                  int* __restrict__ sls)
{
    __shared__ int sl[B_];
    const int tid = threadIdx.x;
    for (int i = tid; i < B_; i += 256) sl[i] = seqlen[i];
    __syncthreads();
    const int b = blockIdx.x * 256 + tid;
    const int v = sl[b];
    int pos = 0;
#pragma unroll 8
    for (int j = 0; j < B_; j++) {
        int u = sl[j];
        pos += (u > v) || (u == v && j < b);
    }
    perm[pos] = b;
    sls[pos]  = v;
}

// =============================================================================
// Kernel 1: HMMA precompute. D[128-row tile, 128 cols] = X @ W-slice via
// mma.sync m16n8k16 bf16->fp32, 3-product hi/lo split. grid=(M/128, 3).
// 8 warps = 2(M) x 4(N); warp tile 64x32 (4x4 atoms); K=128 resident in smem.
// Tiles whose rows are all masked are skipped. NO bias (folded into recurrent).
// =============================================================================
#define BSTR 136                 // bf16 elements per smem row (pad 8)
#define PC_AHI 0
#define PC_ALO (128 * BSTR * 2)
#define PC_BHI (2 * 128 * BSTR * 2)
#define PC_BLO (3 * 128 * BSTR * 2)
#define PC_SMEM (4 * 128 * BSTR * 2)   // 139264 B

__global__ void __launch_bounds__(256, 1) augru_precompute_mma(
    const float* __restrict__ X,
    const __nv_bfloat16* __restrict__ WThi,
    const __nv_bfloat16* __restrict__ WTlo,
    const int* __restrict__ seqlen,
    float* __restrict__ Gx, float* __restrict__ Cx)
{
    const int m0 = blockIdx.x * 128;
    // ---- early skip: all 128 rows masked? ----
    {
        int b1 = m0 / T_;
        int t1 = m0 - b1 * T_;
        bool any = (t1 < seqlen[b1]);
        int b2 = (m0 + 127) / T_;
        if (b2 != b1) any = any || (seqlen[b2] > 0);
        if (!any) return;
    }

    extern __shared__ char smem[];
    const int tid = threadIdx.x;
    const int nt  = blockIdx.y;          // 0,1 -> Gx cols nt*128; 2 -> Cx

    // ---- stage A: X rows -> bf16 hi/lo ----
#pragma unroll
    for (int q = 0; q < 4; q++) {
        int f = q * 256 + tid;           // 1024 float4 total
        int m = f >> 3, k = (f & 7) << 4;    // two float4 per iteration step
        // each f covers 16 floats? No: use 4 floats per f, 1024*4 = 4096... need 16384 floats
        // -> do 4 floats per f with 16 iterations instead:
        (void)m; (void)k;
    }
    // (restructured below: 16 chunks of 4 floats)
#pragma unroll
    for (int q = 0; q < 16; q++) {
        int f = q * 256 + tid;           // 4096 iterations x float4 = 16384 floats
        int m = f >> 5, k = (f & 31) << 2;
        float4 v = *(const float4*)&X[(size_t)(m0 + m) * 128 + k];
        __nv_bfloat16 h0 = __float2bfloat16(v.x), h1 = __float2bfloat16(v.y);
        __nv_bfloat16 h2 = __float2bfloat16(v.z), h3 = __float2bfloat16(v.w);
        uint32_t hv0 = ((uint32_t)__bfloat16_as_ushort(h1) << 16) | __bfloat16_as_ushort(h0);
        uint32_t hv1 = ((uint32_t)__bfloat16_as_ushort(h3) << 16) | __bfloat16_as_ushort(h2);
        __nv_bfloat16 l0 = __float2bfloat16(v.x - __bfloat162float(h0));
        __nv_bfloat16 l1 = __float2bfloat16(v.y - __bfloat162float(h1));
        __nv_bfloat16 l2 = __float2bfloat16(v.z - __bfloat162float(h2));
        __nv_bfloat16 l3 = __float2bfloat16(v.w - __bfloat162float(h3));
        uint32_t lv0 = ((uint32_t)__bfloat16_as_ushort(l1) << 16) | __bfloat16_as_ushort(l0);
        uint32_t lv1 = ((uint32_t)__bfloat16_as_ushort(l3) << 16) | __bfloat16_as_ushort(l2);
        size_t o = ((size_t)m * BSTR + k) * 2;
        *(uint32_t*)(smem + PC_AHI + o) = hv0;
        *(uint32_t*)(smem + PC_AHI + o + 4) = hv1;
        *(uint32_t*)(smem + PC_ALO + o) = lv0;
        *(uint32_t*)(smem + PC_ALO + o + 4) = lv1;
    }
    // ---- stage B: WT rows nt*128 .. +127 (bf16, already split) ----
#pragma unroll
    for (int q = 0; q < 8; q++) {
        int f = q * 256 + tid;           // 2048 x uint4 (8 bf16) = 16384 elems
        int n = f >> 4, k = (f & 15) << 3;
        size_t src = (size_t)(nt * 128 + n) * 128 + k;
        uint4 vh = *(const uint4*)&WThi[src];
        uint4 vl = *(const uint4*)&WTlo[src];
        size_t o = ((size_t)n * BSTR + k) * 2;
        *(uint4*)(smem + PC_BHI + o) = vh;
        *(uint4*)(smem + PC_BLO + o) = vl;
    }
    __syncthreads();

    // ---- warp tiling ----
    const int wid = tid >> 5, lane = tid & 31;
    const int wm = wid >> 2, wn = wid & 3;      // 2 x 4
    const int g = lane >> 2, tig = lane & 3;

    float acc[4][4][4];
#pragma unroll
    for (int i = 0; i < 4; i++)
#pragma unroll
        for (int j = 0; j < 4; j++)
#pragma unroll
            for (int e = 0; e < 4; e++) acc[i][j][e] = 0.0f;

#pragma unroll 1
    for (int prod = 0; prod < 3; prod++) {
        const char* Ab = smem + ((prod == 1) ? PC_ALO : PC_AHI);
        const char* Bb = smem + ((prod == 2) ? PC_BLO : PC_BHI);
#pragma unroll
        for (int ks = 0; ks < 8; ks++) {
            const int k0 = ks * 16 + 2 * tig;
            uint32_t a[4][4], b[4][2];
#pragma unroll
            for (int ma = 0; ma < 4; ma++) {
                int r0 = wm * 64 + ma * 16 + g;
                a[ma][0] = *(const uint32_t*)(Ab + ((size_t)r0 * BSTR + k0) * 2);
                a[ma][1] = *(const uint32_t*)(Ab + ((size_t)(r0 + 8) * BSTR + k0) * 2);
                a[ma][2] = *(const uint32_t*)(Ab + ((size_t)r0 * BSTR + k0 + 8) * 2);
                a[ma][3] = *(const uint32_t*)(Ab + ((size_t)(r0 + 8) * BSTR + k0 + 8) * 2);
            }
#pragma unroll
            for (int na = 0; na < 4; na++) {
                int n0 = wn * 32 + na * 8 + g;
                b[na][0] = *(const uint32_t*)(Bb + ((size_t)n0 * BSTR + k0) * 2);
                b[na][1] = *(const uint32_t*)(Bb + ((size_t)n0 * BSTR + k0 + 8) * 2);
            }
#pragma unroll
            for (int ma = 0; ma < 4; ma++)
#pragma unroll
                for (int na = 0; na < 4; na++)
                    mma16816(acc[ma][na], a[ma][0], a[ma][1], a[ma][2], a[ma][3],
                             b[na][0], b[na][1]);
        }
    }

    // ---- epilogue: direct STG (float2 per atom-row) ----
    float* Out = (nt < 2) ? Gx : Cx;
    const int ldo = (nt < 2) ? 256 : 128;
    const int nc0 = (nt < 2) ? nt * 128 : 0;
#pragma unroll
    for (int ma = 0; ma < 4; ma++) {
        int r = m0 + wm * 64 + ma * 16 + g;
#pragma unroll
        for (int na = 0; na < 4; na++) {
            int col = nc0 + wn * 32 + na * 8 + 2 * tig;
            float2 v0 = make_float2(acc[ma][na][0], acc[ma][na][1]);
            float2 v1 = make_float2(acc[ma][na][2], acc[ma][na][3]);
            *(float2*)&Out[(size_t)r * ldo + col] = v0;
            *(float2*)&Out[(size_t)(r + 8) * ldo + col] = v1;
        }
    }
}

// =============================================================================
// Kernel 2: persistent recurrence (biases folded here; structure from R4).
// =============================================================================
#define BPB      8
#define THR      512
#define KS       132

#define SMEM_REC_FLOATS (256*KS + 128*KS + 3*BPB*KS)
#define SMEM_REC_BYTES  (SMEM_REC_FLOATS * 4)

__global__ void __launch_bounds__(THR, 1) augru_recurrent(
    const float* __restrict__ Gx, const float* __restrict__ Cx,
    const float* __restrict__ att,
    const int* __restrict__ perm, const int* __restrict__ sls,
    const float* __restrict__ Wg, const float* __restrict__ Wc,
    const float* __restrict__ bg, const float* __restrict__ bc,
    float* __restrict__ out)
{
    extern __shared__ float sm[];
    float* WghT = sm;
    float* WchT = WghT + 256 * KS;
    float* hB   = WchT + 128 * KS;
    float* hrB  = hB   + BPB * KS;
    float* uu   = hrB  + BPB * KS;

    const int tid = threadIdx.x;
    const int g0  = blockIdx.x * BPB;

    for (int idx = tid; idx < 128 * 64; idx += THR) {
        int k = idx >> 6, c4 = (idx & 63) << 2;
        float4 v = *(const float4*)&Wg[(size_t)(128 + k) * 256 + c4];
        WghT[(c4 + 0) * KS + k] = v.x; WghT[(c4 + 1) * KS + k] = v.y;
        WghT[(c4 + 2) * KS + k] = v.z; WghT[(c4 + 3) * KS + k] = v.w;
    }
    for (int idx = tid; idx < 128 * 32; idx += THR) {
        int k = idx >> 5, c4 = (idx & 31) << 2;
        float4 v = *(const float4*)&Wc[(size_t)(128 + k) * 128 + c4];
        WchT[(c4 + 0) * KS + k] = v.x; WchT[(c4 + 1) * KS + k] = v.y;
        WchT[(c4 + 2) * KS + k] = v.z; WchT[(c4 + 3) * KS + k] = v.w;
    }
    for (int i = tid; i < 3 * BPB * KS; i += THR) hB[i] = 0.0f;

    const int bq = tid & 3;
    const int cq = tid >> 2;
    const int bb = bq * 2;

    int pb[2], sl[2];
    pb[0] = perm[g0 + bb];     pb[1] = perm[g0 + bb + 1];
    sl[0] = sls[g0 + bb];      sl[1] = sls[g0 + bb + 1];
    const int maxsl = sls[g0];

    const float bgr = bg[cq], bgu = bg[128 + cq], bcv = bc[cq];

    const float* hp0 = hB  + (size_t)bb * KS;
    const float* hp1 = hB  + (size_t)(bb + 1) * KS;
    const float* rp0 = hrB + (size_t)bb * KS;
    const float* rp1 = hrB + (size_t)(bb + 1) * KS;
    const float* wr  = WghT + (size_t)cq * KS;
    const float* wu  = WghT + (size_t)(cq + 128) * KS;
    const float* wc  = WchT + (size_t)cq * KS;

    const size_t rb0 = (size_t)pb[0] * T_;
    const size_t rb1 = (size_t)pb[1] * T_;

    float pgx0r = 0, pgx0u = 0, pgx1r = 0, pgx1u = 0;
    float pat0 = 0, pat1 = 0, pcx0 = 0, pcx1 = 0;
    if (maxsl > 0) {
        pgx0r = Gx[rb0 * 256 + cq];        pgx0u = Gx[rb0 * 256 + 128 + cq];
        pgx1r = Gx[rb1 * 256 + cq];        pgx1u = Gx[rb1 * 256 + 128 + cq];
        pat0  = att[rb0];                  pat1  = att[rb1];
        pcx0  = Cx[rb0 * 128 + cq];        pcx1  = Cx[rb1 * 128 + cq];
    }

    __syncthreads();

    for (int t = 0; t < maxsl; t++) {
        const float gx0r = pgx0r, gx0u = pgx0u, gx1r = pgx1r, gx1u = pgx1u;
        const float at0 = pat0, at1 = pat1, cx0 = pcx0, cx1 = pcx1;

        if (t + 1 < maxsl) {
            const size_t n0 = (rb0 + t + 1), n1 = (rb1 + t + 1);
            pgx0r = Gx[n0 * 256 + cq];     pgx0u = Gx[n0 * 256 + 128 + cq];
            pgx1r = Gx[n1 * 256 + cq];     pgx1u = Gx[n1 * 256 + 128 + cq];
            pat0  = att[n0];               pat1  = att[n1];
            pcx0  = Cx[n0 * 128 + cq];     pcx1  = Cx[n1 * 128 + cq];
        }

        ull a0r = 0, a0u = 0, a1r = 0, a1u = 0;
#pragma unroll 8
        for (int k = 0; k < 128; k += 4) {
            ulonglong2 h0 = *(const ulonglong2*)&hp0[k];
            ulonglong2 h1 = *(const ulonglong2*)&hp1[k];
            ulonglong2 w0 = *(const ulonglong2*)&wr[k];
            ulonglong2 w1 = *(const ulonglong2*)&wu[k];
            fma2(a0r, h0.x, w0.x); fma2(a0r, h0.y, w0.y);
            fma2(a0u, h0.x, w1.x); fma2(a0u, h0.y, w1.y);
            fma2(a1r, h1.x, w0.x); fma2(a1r, h1.y, w0.y);
            fma2(a1u, h1.x, w1.x); fma2(a1u, h1.y, w1.y);
        }
        float lo, hi, g0r, g0u, g1r, g1u;
        unpack2(a0r, lo, hi); g0r = lo + hi;
        unpack2(a0u, lo, hi); g0u = lo + hi;
        unpack2(a1r, lo, hi); g1r = lo + hi;
        unpack2(a1u, lo, hi); g1u = lo + hi;

        {
            float r0 = sigmoid_fast(g0r + gx0r + bgr);
            float r1 = sigmoid_fast(g1r + gx1r + bgr);
            hrB[bb * KS + cq]       = r0 * hp0[cq];
            hrB[(bb + 1) * KS + cq] = r1 * hp1[cq];
            uu[bb * KS + cq]        = at0 * sigmoid_fast(g0u + gx0u + bgu);
            uu[(bb + 1) * KS + cq]  = at1 * sigmoid_fast(g1u + gx1u + bgu);
        }
        __syncthreads();

        ull c0a = 0, c1a = 0;
#pragma unroll 8
        for (int k = 0; k < 128; k += 4) {
            ulonglong2 h0 = *(const ulonglong2*)&rp0[k];
            ulonglong2 h1 = *(const ulonglong2*)&rp1[k];
            ulonglong2 w  = *(const ulonglong2*)&wc[k];
            fma2(c0a, h0.x, w.x); fma2(c0a, h0.y, w.y);
            fma2(c1a, h1.x, w.x); fma2(c1a, h1.y, w.y);
        }
        float cc0, cc1;
        unpack2(c0a, lo, hi); cc0 = lo + hi;
        unpack2(c1a, lo, hi); cc1 = lo + hi;

        {
            float cv0 = tanh_fast(cc0 + cx0 + bcv);
            float cv1 = tanh_fast(cc1 + cx1 + bcv);
            float u0 = uu[bb * KS + cq],       u1 = uu[(bb + 1) * KS + cq];
            float h0 = hB[bb * KS + cq],       h1 = hB[(bb + 1) * KS + cq];
            float hn0 = (1.0f - u0) * h0 + u0 * cv0;
            float hn1 = (1.0f - u1) * h1 + u1 * cv1;
            bool v0 = (t < sl[0]), v1 = (t < sl[1]);
            out[(rb0 + t) * 128 + cq] = v0 ? hn0 : 0.0f;
            out[(rb1 + t) * 128 + cq] = v1 ? hn1 : 0.0f;
            hB[bb * KS + cq]       = v0 ? hn0 : h0;
            hB[(bb + 1) * KS + cq] = v1 ? hn1 : h1;
        }
        __syncthreads();
    }

    for (int idx = tid; idx < (T_ - maxsl) * BPB * 32; idx += THR) {
        int t  = maxsl + idx / (BPB * 32);
        int r  = idx % (BPB * 32);
        int i  = r >> 5;
        int j4 = (r & 31) << 2;
        int b  = perm[g0 + i];
        *(float4*)&out[((size_t)b * T_ + t) * 128 + j4] = make_float4(0.f, 0.f, 0.f, 0.f);
    }
}

// =============================================================================
extern "C" void kernel_launch(void* const* d_in, const int* in_sizes, int n_in,
                              void* d_out, int out_size)
{
    (void)in_sizes; (void)n_in; (void)out_size;
    const float* X      = (const float*)d_in[0];
    const float* att    = (const float*)d_in[1];
    const int*   seqlen = (const int*)  d_in[2];
    const float* Wg     = (const float*)d_in[3];
    const float* bg     = (const float*)d_in[4];
    const float* Wc     = (const float*)d_in[5];
    const float* bc     = (const float*)d_in[6];
    float* out          = (float*)d_out;

    float *Gx, *Cx; int *perm, *sls; __nv_bfloat16 *WThi, *WTlo;
    cudaGetSymbolAddress((void**)&Gx,   g_Gx);
    cudaGetSymbolAddress((void**)&Cx,   g_Cx);
    cudaGetSymbolAddress((void**)&perm, g_perm);
    cudaGetSymbolAddress((void**)&sls,  g_sls);
    cudaGetSymbolAddress((void**)&WThi, g_WThi);
    cudaGetSymbolAddress((void**)&WTlo, g_WTlo);

    augru_wprep<<<12, 256>>>(Wg, Wc, WThi, WTlo);
    augru_sort<<<B_ / 256, 256>>>(seqlen, perm, sls);

    cudaFuncSetAttribute(augru_precompute_mma,
                         cudaFuncAttributeMaxDynamicSharedMemorySize, PC_SMEM);
    dim3 gpre(M_ / 128, 3);
    augru_precompute_mma<<<gpre, 256, PC_SMEM>>>(X, WThi, WTlo, seqlen, Gx, Cx);

    cudaFuncSetAttribute(augru_recurrent,
                         cudaFuncAttributeMaxDynamicSharedMemorySize, SMEM_REC_BYTES);
    augru_recurrent<<<B_ / BPB, THR, SMEM_REC_BYTES>>>(Gx, Cx, att, perm, sls,
                                                       Wg, Wc, bg, bc, out);
}

// round 8
// speedup vs baseline: 2.4557x; 1.4699x over previous
#include <cuda_runtime.h>
#include <cuda_bf16.h>
#include <cstdint>

#define B_   2048
#define T_   200
#define D_   128
#define H_   128
#define M_   (B_ * T_)          // 409600 rows

typedef unsigned long long ull;

// ---------------- scratch (static device arrays; no allocation) ----------------
__device__ float g_Gx[(size_t)M_ * 256];   // x-part of gate pre-activations (NO bias)
__device__ float g_Cx[(size_t)M_ * 128];   // x-part of candidate pre-activations (NO bias)
__device__ int   g_perm[B_];
__device__ int   g_sls[B_];
// Full W^T hi/lo: [n (384)][k (256)].  k 0..127 = x-part (precompute), 128..255 = h-part (recurrent)
__device__ __align__(16) __nv_bfloat16 g_WThi[384 * 256];
__device__ __align__(16) __nv_bfloat16 g_WTlo[384 * 256];

// ---------------- math helpers ---------------------------------------------------
__device__ __forceinline__ float sigmoid_fast(float x) {
    float e;
    asm("ex2.approx.f32 %0, %1;" : "=f"(e) : "f"(-1.4426950408889634f * x));
    float r;
    asm("rcp.approx.f32 %0, %1;" : "=f"(r) : "f"(1.0f + e));
    return r;
}
__device__ __forceinline__ float tanh_fast(float x) {
    return fmaf(2.0f, sigmoid_fast(2.0f * x), -1.0f);
}
__device__ __forceinline__ uint32_t bf16pack(float a, float b) {
    __nv_bfloat16 ha = __float2bfloat16(a), hb = __float2bfloat16(b);
    return ((uint32_t)__bfloat16_as_ushort(hb) << 16) | __bfloat16_as_ushort(ha);
}

// ---------------- warp-level bf16 MMA (sm_80+, legal on compute_103) -------------
__device__ __forceinline__ void mma16816(float* c,
    uint32_t a0, uint32_t a1, uint32_t a2, uint32_t a3,
    uint32_t b0, uint32_t b1)
{
    asm volatile(
        "mma.sync.aligned.m16n8k16.row.col.f32.bf16.bf16.f32 "
        "{%0,%1,%2,%3}, {%4,%5,%6,%7}, {%8,%9}, {%0,%1,%2,%3};"
        : "+f"(c[0]), "+f"(c[1]), "+f"(c[2]), "+f"(c[3])
        : "r"(a0), "r"(a1), "r"(a2), "r"(a3), "r"(b0), "r"(b1));
}

// =============================================================================
// Kernel 0a: FULL W transpose + bf16 hi/lo split. WT[n][k] = W[k][n], k 0..255.
// n: 0..255 -> Wg cols, 256..383 -> Wc cols. 12 blocks x 256 threads.
// =============================================================================
__global__ void __launch_bounds__(256) augru_wprep(
    const float* __restrict__ Wg, const float* __restrict__ Wc,
    __nv_bfloat16* __restrict__ WThi, __nv_bfloat16* __restrict__ WTlo)
{
    __shared__ float s[32][33];
    const int n0 = blockIdx.x * 32;
    const int tx = threadIdx.x & 31, ty = threadIdx.x >> 5;   // 32 x 8
    for (int k0 = 0; k0 < 256; k0 += 32) {
        for (int rr = 0; rr < 32; rr += 8) {
            int k = k0 + ty + rr, n = n0 + tx;
            s[ty + rr][tx] = (n0 < 256) ? Wg[(size_t)k * 256 + n]
                                        : Wc[(size_t)k * 128 + (n - 256)];
        }
        __syncthreads();
        for (int rr = 0; rr < 32; rr += 8) {
            int n = n0 + ty + rr, k = k0 + tx;
            float v = s[tx][ty + rr];
            __nv_bfloat16 hi = __float2bfloat16(v);
            float lo = v - __bfloat162float(hi);
            WThi[(size_t)n * 256 + k] = hi;
            WTlo[(size_t)n * 256 + k] = __float2bfloat16(lo);
        }
        __syncthreads();
    }
}

// =============================================================================
// Kernel 0b: parallel deterministic sort of batches by seq_len, DESCENDING.
// =============================================================================
__global__ void __launch_bounds__(256) augru_sort(const int* __restrict__ seqlen,
                                                  int* __restrict__ perm,
                                                  int* __restrict__ sls)
{
    __shared__ int sl[B_];
    const int tid = threadIdx.x;
    for (int i = tid; i < B_; i += 256) sl[i] = seqlen[i];
    __syncthreads();
    const int b = blockIdx.x * 256 + tid;
    const int v = sl[b];
    int pos = 0;
#pragma unroll 8
    for (int j = 0; j < B_; j++) {
        int u = sl[j];
        pos += (u > v) || (u == v && j < b);
    }
    perm[pos] = b;
    sls[pos]  = v;
}

// =============================================================================
// Kernel 1: HMMA precompute (unchanged from R6 except WT stride 256).
// =============================================================================
#define BSTR 136
#define PC_AHI 0
#define PC_ALO (128 * BSTR * 2)
#define PC_BHI (2 * 128 * BSTR * 2)
#define PC_BLO (3 * 128 * BSTR * 2)
#define PC_SMEM (4 * 128 * BSTR * 2)   // 139264 B

__global__ void __launch_bounds__(256, 1) augru_precompute_mma(
    const float* __restrict__ X,
    const __nv_bfloat16* __restrict__ WThi,
    const __nv_bfloat16* __restrict__ WTlo,
    const int* __restrict__ seqlen,
    float* __restrict__ Gx, float* __restrict__ Cx)
{
    const int m0 = blockIdx.x * 128;
    {
        int b1 = m0 / T_;
        int t1 = m0 - b1 * T_;
        bool any = (t1 < seqlen[b1]);
        int b2 = (m0 + 127) / T_;
        if (b2 != b1) any = any || (seqlen[b2] > 0);
        if (!any) return;
    }

    extern __shared__ char smem[];
    const int tid = threadIdx.x;
    const int nt  = blockIdx.y;          // 0,1 -> Gx cols nt*128; 2 -> Cx

#pragma unroll
    for (int q = 0; q < 16; q++) {
        int f = q * 256 + tid;
        int m = f >> 5, k = (f & 31) << 2;
        float4 v = *(const float4*)&X[(size_t)(m0 + m) * 128 + k];
        __nv_bfloat16 h0 = __float2bfloat16(v.x), h1 = __float2bfloat16(v.y);
        __nv_bfloat16 h2 = __float2bfloat16(v.z), h3 = __float2bfloat16(v.w);
        uint32_t hv0 = ((uint32_t)__bfloat16_as_ushort(h1) << 16) | __bfloat16_as_ushort(h0);
        uint32_t hv1 = ((uint32_t)__bfloat16_as_ushort(h3) << 16) | __bfloat16_as_ushort(h2);
        __nv_bfloat16 l0 = __float2bfloat16(v.x - __bfloat162float(h0));
        __nv_bfloat16 l1 = __float2bfloat16(v.y - __bfloat162float(h1));
        __nv_bfloat16 l2 = __float2bfloat16(v.z - __bfloat162float(h2));
        __nv_bfloat16 l3 = __float2bfloat16(v.w - __bfloat162float(h3));
        uint32_t lv0 = ((uint32_t)__bfloat16_as_ushort(l1) << 16) | __bfloat16_as_ushort(l0);
        uint32_t lv1 = ((uint32_t)__bfloat16_as_ushort(l3) << 16) | __bfloat16_as_ushort(l2);
        size_t o = ((size_t)m * BSTR + k) * 2;
        *(uint32_t*)(smem + PC_AHI + o) = hv0;
        *(uint32_t*)(smem + PC_AHI + o + 4) = hv1;
        *(uint32_t*)(smem + PC_ALO + o) = lv0;
        *(uint32_t*)(smem + PC_ALO + o + 4) = lv1;
    }
#pragma unroll
    for (int q = 0; q < 8; q++) {
        int f = q * 256 + tid;
        int n = f >> 4, k = (f & 15) << 3;
        size_t src = (size_t)(nt * 128 + n) * 256 + k;    // x-part slice k 0..127
        uint4 vh = *(const uint4*)&WThi[src];
        uint4 vl = *(const uint4*)&WTlo[src];
        size_t o = ((size_t)n * BSTR + k) * 2;
        *(uint4*)(smem + PC_BHI + o) = vh;
        *(uint4*)(smem + PC_BLO + o) = vl;
    }
    __syncthreads();

    const int wid = tid >> 5, lane = tid & 31;
    const int wm = wid >> 2, wn = wid & 3;
    const int g = lane >> 2, tig = lane & 3;

    float acc[4][4][4];
#pragma unroll
    for (int i = 0; i < 4; i++)
#pragma unroll
        for (int j = 0; j < 4; j++)
#pragma unroll
            for (int e = 0; e < 4; e++) acc[i][j][e] = 0.0f;

#pragma unroll 1
    for (int prod = 0; prod < 3; prod++) {
        const char* Ab = smem + ((prod == 1) ? PC_ALO : PC_AHI);
        const char* Bb = smem + ((prod == 2) ? PC_BLO : PC_BHI);
#pragma unroll
        for (int ks = 0; ks < 8; ks++) {
            const int k0 = ks * 16 + 2 * tig;
            uint32_t a[4][4], b[4][2];
#pragma unroll
            for (int ma = 0; ma < 4; ma++) {
                int r0 = wm * 64 + ma * 16 + g;
                a[ma][0] = *(const uint32_t*)(Ab + ((size_t)r0 * BSTR + k0) * 2);
                a[ma][1] = *(const uint32_t*)(Ab + ((size_t)(r0 + 8) * BSTR + k0) * 2);
                a[ma][2] = *(const uint32_t*)(Ab + ((size_t)r0 * BSTR + k0 + 8) * 2);
                a[ma][3] = *(const uint32_t*)(Ab + ((size_t)(r0 + 8) * BSTR + k0 + 8) * 2);
            }
#pragma unroll
            for (int na = 0; na < 4; na++) {
                int n0 = wn * 32 + na * 8 + g;
                b[na][0] = *(const uint32_t*)(Bb + ((size_t)n0 * BSTR + k0) * 2);
                b[na][1] = *(const uint32_t*)(Bb + ((size_t)n0 * BSTR + k0 + 8) * 2);
            }
#pragma unroll
            for (int ma = 0; ma < 4; ma++)
#pragma unroll
                for (int na = 0; na < 4; na++)
                    mma16816(acc[ma][na], a[ma][0], a[ma][1], a[ma][2], a[ma][3],
                             b[na][0], b[na][1]);
        }
    }

    float* Out = (nt < 2) ? Gx : Cx;
    const int ldo = (nt < 2) ? 256 : 128;
    const int nc0 = (nt < 2) ? nt * 128 : 0;
#pragma unroll
    for (int ma = 0; ma < 4; ma++) {
        int r = m0 + wm * 64 + ma * 16 + g;
#pragma unroll
        for (int na = 0; na < 4; na++) {
            int col = nc0 + wn * 32 + na * 8 + 2 * tig;
            float2 v0 = make_float2(acc[ma][na][0], acc[ma][na][1]);
            float2 v1 = make_float2(acc[ma][na][2], acc[ma][na][3]);
            *(float2*)&Out[(size_t)r * ldo + col] = v0;
            *(float2*)&Out[(size_t)(r + 8) * ldo + col] = v1;
        }
    }
}

// =============================================================================
// Kernel 2: HMMA recurrence. BPB=16 sorted batches/block, 128 blocks (1 wave),
// 512 threads (16 warps). All weights bf16 hi/lo [col][k] in smem (stride 136,
// conflict-free fragments). h state in registers of warps 0-7 (fragment-owner
// mapping identical for reset gate, candidate and h-update). 3-product split.
// =============================================================================
#define BPB 16
#define THR 512
// smem byte offsets
#define O_WGH 0
#define O_WGL 69632
#define O_WCH 139264
#define O_WCL 174080
#define O_AH  208896
#define O_AL  213248
#define O_UU  217600
#define REC_SMEM 226048    // O_UU + 16*132*4

__global__ void __launch_bounds__(THR, 1) augru_recurrent_tc(
    const float* __restrict__ Gx, const float* __restrict__ Cx,
    const float* __restrict__ att,
    const int* __restrict__ perm, const int* __restrict__ sls,
    const __nv_bfloat16* __restrict__ WThi, const __nv_bfloat16* __restrict__ WTlo,
    const float* __restrict__ bg, const float* __restrict__ bc,
    float* __restrict__ out)
{
    extern __shared__ char smem[];
    const int tid = threadIdx.x;
    const int g0  = blockIdx.x * BPB;

    // ---- stage recurrent weights (h-part, k 128..255) as [col][136] bf16 ----
    for (int i = tid; i < 256 * 16; i += THR) {
        int col = i >> 4, q = (i & 15);
        *(uint4*)(smem + O_WGH + col * 272 + q * 16) = *(const uint4*)&WThi[(size_t)col * 256 + 128 + q * 8];
        *(uint4*)(smem + O_WGL + col * 272 + q * 16) = *(const uint4*)&WTlo[(size_t)col * 256 + 128 + q * 8];
    }
    for (int i = tid; i < 128 * 16; i += THR) {
        int col = i >> 4, q = (i & 15);
        *(uint4*)(smem + O_WCH + col * 272 + q * 16) = *(const uint4*)&WThi[(size_t)(256 + col) * 256 + 128 + q * 8];
        *(uint4*)(smem + O_WCL + col * 272 + q * 16) = *(const uint4*)&WTlo[(size_t)(256 + col) * 256 + 128 + q * 8];
    }
    // zero A buffers (h = 0)
    for (int i = tid; i < (4352 * 2) / 16; i += THR)
        *(uint4*)(smem + O_AH + i * 16) = make_uint4(0, 0, 0, 0);

    const int wid = tid >> 5, lane = tid & 31;
    const int g = lane >> 2, tig = lane & 3;
    const int nbase = wid * 16;                 // gate cols [nbase, nbase+16)
    const bool lowW = (wid < 8);
    const int ucol = nbase - 128;               // update-col base (warps 8-15)

    const int pb_lo = perm[g0 + g], pb_hi = perm[g0 + g + 8];
    const int sl_lo = sls[g0 + g],  sl_hi = sls[g0 + g + 8];
    const int maxsl = sls[g0];
    const size_t rb_lo = (size_t)pb_lo * T_, rb_hi = (size_t)pb_hi * T_;

    // biases (per-lane constants)
    float bgv[2][2], bcv2[2][2];
#pragma unroll
    for (int nt = 0; nt < 2; nt++) {
        int cp = (lowW ? nbase : nbase) + nt * 8 + 2 * tig;   // 0..255 gate col
        bgv[nt][0] = bg[cp]; bgv[nt][1] = bg[cp + 1];
        if (lowW) { bcv2[nt][0] = bc[cp]; bcv2[nt][1] = bc[cp + 1]; }
        else      { bcv2[nt][0] = bcv2[nt][1] = 0.0f; }
    }

    // h state registers (warps 0-7): h[nt][e], e: 0=(g,c),1=(g,c+1),2=(g+8,c),3=(g+8,c+1)
    float hreg[2][4];
#pragma unroll
    for (int nt = 0; nt < 2; nt++)
#pragma unroll
        for (int e = 0; e < 4; e++) hreg[nt][e] = 0.0f;

    // prefetch buffers: warps 0-7: pA = Gx reset pairs, pB = Cx pairs
    //                   warps 8-15: pA = Gx update pairs, pB.x/.y unused except att
    float2 pA[2][2], pB[2][2];                  // [row(lo/hi)][nt]
    float patt_lo = 0.0f, patt_hi = 0.0f;
    if (maxsl > 0) {
#pragma unroll
        for (int nt = 0; nt < 2; nt++) {
            int cp = nbase + nt * 8 + 2 * tig;   // gate col (0..255)
            pA[0][nt] = *(const float2*)&Gx[rb_lo * 256 + cp];
            pA[1][nt] = *(const float2*)&Gx[rb_hi * 256 + cp];
            if (lowW) {
                pB[0][nt] = *(const float2*)&Cx[rb_lo * 128 + cp];
                pB[1][nt] = *(const float2*)&Cx[rb_hi * 128 + cp];
            }
        }
        if (!lowW) { patt_lo = att[rb_lo]; patt_hi = att[rb_hi]; }
    }

    __syncthreads();   // weights + A zero visible

    for (int t = 0; t < maxsl; t++) {
        // consume current prefetch
        float2 cA[2][2], cB[2][2];
        float att_lo = patt_lo, att_hi = patt_hi;
#pragma unroll
        for (int r = 0; r < 2; r++)
#pragma unroll
            for (int nt = 0; nt < 2; nt++) { cA[r][nt] = pA[r][nt]; cB[r][nt] = pB[r][nt]; }

        // issue t+1 prefetch (overlaps gate MMAs)
        if (t + 1 < maxsl) {
            const size_t n_lo = rb_lo + t + 1, n_hi = rb_hi + t + 1;
#pragma unroll
            for (int nt = 0; nt < 2; nt++) {
                int cp = nbase + nt * 8 + 2 * tig;
                pA[0][nt] = *(const float2*)&Gx[n_lo * 256 + cp];
                pA[1][nt] = *(const float2*)&Gx[n_hi * 256 + cp];
                if (lowW) {
                    pB[0][nt] = *(const float2*)&Cx[n_lo * 128 + cp];
                    pB[1][nt] = *(const float2*)&Cx[n_hi * 128 + cp];
                }
            }
            if (!lowW) { patt_lo = att[n_lo]; patt_hi = att[n_hi]; }
        }

        // ---- gate MMAs: all warps, cols [nbase, nbase+16), A = h hi/lo ----
        float acc[2][4];
#pragma unroll
        for (int nt = 0; nt < 2; nt++)
#pragma unroll
            for (int e = 0; e < 4; e++) acc[nt][e] = 0.0f;

#pragma unroll
        for (int k0 = 0; k0 < 128; k0 += 16) {
            const int ka = k0 + 2 * tig;
            uint32_t ah0 = *(const uint32_t*)(smem + O_AH + g * 272 + ka * 2);
            uint32_t ah1 = *(const uint32_t*)(smem + O_AH + (g + 8) * 272 + ka * 2);
            uint32_t ah2 = *(const uint32_t*)(smem + O_AH + g * 272 + (ka + 8) * 2);
            uint32_t ah3 = *(const uint32_t*)(smem + O_AH + (g + 8) * 272 + (ka + 8) * 2);
            uint32_t al0 = *(const uint32_t*)(smem + O_AL + g * 272 + ka * 2);
            uint32_t al1 = *(const uint32_t*)(smem + O_AL + (g + 8) * 272 + ka * 2);
            uint32_t al2 = *(const uint32_t*)(smem + O_AL + g * 272 + (ka + 8) * 2);
            uint32_t al3 = *(const uint32_t*)(smem + O_AL + (g + 8) * 272 + (ka + 8) * 2);
#pragma unroll
            for (int nt = 0; nt < 2; nt++) {
                int col = nbase + nt * 8 + g;
                uint32_t bh0 = *(const uint32_t*)(smem + O_WGH + col * 272 + ka * 2);
                uint32_t bh1 = *(const uint32_t*)(smem + O_WGH + col * 272 + (ka + 8) * 2);
                uint32_t bl0 = *(const uint32_t*)(smem + O_WGL + col * 272 + ka * 2);
                uint32_t bl1 = *(const uint32_t*)(smem + O_WGL + col * 272 + (ka + 8) * 2);
                mma16816(acc[nt], ah0, ah1, ah2, ah3, bh0, bh1);
                mma16816(acc[nt], al0, al1, al2, al3, bh0, bh1);
                mma16816(acc[nt], ah0, ah1, ah2, ah3, bl0, bl1);
            }
        }
        __syncthreads();   // all gate reads of A done

        // ---- gate epilogue ----
        if (lowW) {
            // reset gate -> rh = r * h  -> A buffer (bf16 hi/lo)
#pragma unroll
            for (int nt = 0; nt < 2; nt++) {
                int cp = nbase + nt * 8 + 2 * tig;
                float r00 = sigmoid_fast(acc[nt][0] + cA[0][nt].x + bgv[nt][0]);
                float r01 = sigmoid_fast(acc[nt][1] + cA[0][nt].y + bgv[nt][1]);
                float r10 = sigmoid_fast(acc[nt][2] + cA[1][nt].x + bgv[nt][0]);
                float r11 = sigmoid_fast(acc[nt][3] + cA[1][nt].y + bgv[nt][1]);
                float rh00 = r00 * hreg[nt][0], rh01 = r01 * hreg[nt][1];
                float rh10 = r10 * hreg[nt][2], rh11 = r11 * hreg[nt][3];
                uint32_t hi0 = bf16pack(rh00, rh01);
                uint32_t hi1 = bf16pack(rh10, rh11);
                float l00 = rh00 - __bfloat162float(__ushort_as_bfloat16((unsigned short)(hi0 & 0xFFFF)));
                float l01 = rh01 - __bfloat162float(__ushort_as_bfloat16((unsigned short)(hi0 >> 16)));
                float l10 = rh10 - __bfloat162float(__ushort_as_bfloat16((unsigned short)(hi1 & 0xFFFF)));
                float l11 = rh11 - __bfloat162float(__ushort_as_bfloat16((unsigned short)(hi1 >> 16)));
                *(uint32_t*)(smem + O_AH + g * 272 + cp * 2)       = hi0;
                *(uint32_t*)(smem + O_AH + (g + 8) * 272 + cp * 2) = hi1;
                *(uint32_t*)(smem + O_AL + g * 272 + cp * 2)       = bf16pack(l00, l01);
                *(uint32_t*)(smem + O_AL + (g + 8) * 272 + cp * 2) = bf16pack(l10, l11);
            }
        } else {
            // update gate -> u = att * sigmoid -> UU (fp32)
#pragma unroll
            for (int nt = 0; nt < 2; nt++) {
                int cp = ucol + nt * 8 + 2 * tig;
                float u00 = att_lo * sigmoid_fast(acc[nt][0] + cA[0][nt].x + bgv[nt][0]);
                float u01 = att_lo * sigmoid_fast(acc[nt][1] + cA[0][nt].y + bgv[nt][1]);
                float u10 = att_hi * sigmoid_fast(acc[nt][2] + cA[1][nt].x + bgv[nt][0]);
                float u11 = att_hi * sigmoid_fast(acc[nt][3] + cA[1][nt].y + bgv[nt][1]);
                *(float2*)(smem + O_UU + (g * 132 + cp) * 4)       = make_float2(u00, u01);
                *(float2*)(smem + O_UU + ((g + 8) * 132 + cp) * 4) = make_float2(u10, u11);
            }
        }
        __syncthreads();   // rh + uu ready

        // ---- candidate MMAs: warps 0-7, cols [nbase, nbase+16), A = rh ----
        if (lowW) {
#pragma unroll
            for (int nt = 0; nt < 2; nt++)
#pragma unroll
                for (int e = 0; e < 4; e++) acc[nt][e] = 0.0f;
#pragma unroll
            for (int k0 = 0; k0 < 128; k0 += 16) {
                const int ka = k0 + 2 * tig;
                uint32_t ah0 = *(const uint32_t*)(smem + O_AH + g * 272 + ka * 2);
                uint32_t ah1 = *(const uint32_t*)(smem + O_AH + (g + 8) * 272 + ka * 2);
                uint32_t ah2 = *(const uint32_t*)(smem + O_AH + g * 272 + (ka + 8) * 2);
                uint32_t ah3 = *(const uint32_t*)(smem + O_AH + (g + 8) * 272 + (ka + 8) * 2);
                uint32_t al0 = *(const uint32_t*)(smem + O_AL + g * 272 + ka * 2);
                uint32_t al1 = *(const uint32_t*)(smem + O_AL + (g + 8) * 272 + ka * 2);
                uint32_t al2 = *(const uint32_t*)(smem + O_AL + g * 272 + (ka + 8) * 2);
                uint32_t al3 = *(const uint32_t*)(smem + O_AL + (g + 8) * 272 + (ka + 8) * 2);
#pragma unroll
                for (int nt = 0; nt < 2; nt++) {
                    int col = nbase + nt * 8 + g;
                    uint32_t bh0 = *(const uint32_t*)(smem + O_WCH + col * 272 + ka * 2);
                    uint32_t bh1 = *(const uint32_t*)(smem + O_WCH + col * 272 + (ka + 8) * 2);
                    uint32_t bl0 = *(const uint32_t*)(smem + O_WCL + col * 272 + ka * 2);
                    uint32_t bl1 = *(const uint32_t*)(smem + O_WCL + col * 272 + (ka + 8) * 2);
                    mma16816(acc[nt], ah0, ah1, ah2, ah3, bh0, bh1);
                    mma16816(acc[nt], al0, al1, al2, al3, bh0, bh1);
                    mma16816(acc[nt], ah0, ah1, ah2, ah3, bl0, bl1);
                }
            }
        }
        __syncthreads();   // candidate reads of A (rh) done

        // ---- candidate epilogue: h update + masked output + write new h to A ----
        if (lowW) {
            const bool v_lo = (t < sl_lo), v_hi = (t < sl_hi);
#pragma unroll
            for (int nt = 0; nt < 2; nt++) {
                int cp = nbase + nt * 8 + 2 * tig;
                float c00 = tanh_fast(acc[nt][0] + cB[0][nt].x + bcv2[nt][0]);
                float c01 = tanh_fast(acc[nt][1] + cB[0][nt].y + bcv2[nt][1]);
                float c10 = tanh_fast(acc[nt][2] + cB[1][nt].x + bcv2[nt][0]);
                float c11 = tanh_fast(acc[nt][3] + cB[1][nt].y + bcv2[nt][1]);
                float2 u_lo = *(const float2*)(smem + O_UU + (g * 132 + cp) * 4);
                float2 u_hi = *(const float2*)(smem + O_UU + ((g + 8) * 132 + cp) * 4);
                float hn00 = (1.0f - u_lo.x) * hreg[nt][0] + u_lo.x * c00;
                float hn01 = (1.0f - u_lo.y) * hreg[nt][1] + u_lo.y * c01;
                float hn10 = (1.0f - u_hi.x) * hreg[nt][2] + u_hi.x * c10;
                float hn11 = (1.0f - u_hi.y) * hreg[nt][3] + u_hi.y * c11;
                *(float2*)&out[(rb_lo + t) * 128 + cp] = v_lo ? make_float2(hn00, hn01)
                                                              : make_float2(0.f, 0.f);
                *(float2*)&out[(rb_hi + t) * 128 + cp] = v_hi ? make_float2(hn10, hn11)
                                                              : make_float2(0.f, 0.f);
                hreg[nt][0] = v_lo ? hn00 : hreg[nt][0];
                hreg[nt][1] = v_lo ? hn01 : hreg[nt][1];
                hreg[nt][2] = v_hi ? hn10 : hreg[nt][2];
                hreg[nt][3] = v_hi ? hn11 : hreg[nt][3];
                // write new h (bf16 hi/lo) into A for next step's gate
                uint32_t hi0 = bf16pack(hreg[nt][0], hreg[nt][1]);
                uint32_t hi1 = bf16pack(hreg[nt][2], hreg[nt][3]);
                float l00 = hreg[nt][0] - __bfloat162float(__ushort_as_bfloat16((unsigned short)(hi0 & 0xFFFF)));
                float l01 = hreg[nt][1] - __bfloat162float(__ushort_as_bfloat16((unsigned short)(hi0 >> 16)));
                float l10 = hreg[nt][2] - __bfloat162float(__ushort_as_bfloat16((unsigned short)(hi1 & 0xFFFF)));
                float l11 = hreg[nt][3] - __bfloat162float(__ushort_as_bfloat16((unsigned short)(hi1 >> 16)));
                *(uint32_t*)(smem + O_AH + g * 272 + cp * 2)       = hi0;
                *(uint32_t*)(smem + O_AH + (g + 8) * 272 + cp * 2) = hi1;
                *(uint32_t*)(smem + O_AL + g * 272 + cp * 2)       = bf16pack(l00, l01);
                *(uint32_t*)(smem + O_AL + (g + 8) * 272 + cp * 2) = bf16pack(l10, l11);
            }
        }
        __syncthreads();   // new h visible to all warps' next gate MMAs
    }

    // ---- zero tail: t in [maxsl, T) for all 16 batches ----
    for (int idx = tid; idx < (T_ - maxsl) * BPB * 32; idx += THR) {
        int t  = maxsl + idx / (BPB * 32);
        int r  = idx % (BPB * 32);
        int i  = r >> 5;
        int j4 = (r & 31) << 2;
        int b  = perm[g0 + i];
        *(float4*)&out[((size_t)b * T_ + t) * 128 + j4] = make_float4(0.f, 0.f, 0.f, 0.f);
    }
}

// =============================================================================
extern "C" void kernel_launch(void* const* d_in, const int* in_sizes, int n_in,
                              void* d_out, int out_size)
{
    (void)in_sizes; (void)n_in; (void)out_size;
    const float* X      = (const float*)d_in[0];
    const float* att    = (const float*)d_in[1];
    const int*   seqlen = (const int*)  d_in[2];
    const float* Wg     = (const float*)d_in[3];
    const float* bg     = (const float*)d_in[4];
    const float* Wc     = (const float*)d_in[5];
    const float* bc     = (const float*)d_in[6];
    float* out          = (float*)d_out;

    float *Gx, *Cx; int *perm, *sls; __nv_bfloat16 *WThi, *WTlo;
    cudaGetSymbolAddress((void**)&Gx,   g_Gx);
    cudaGetSymbolAddress((void**)&Cx,   g_Cx);
    cudaGetSymbolAddress((void**)&perm, g_perm);
    cudaGetSymbolAddress((void**)&sls,  g_sls);
    cudaGetSymbolAddress((void**)&WThi, g_WThi);
    cudaGetSymbolAddress((void**)&WTlo, g_WTlo);

    augru_wprep<<<12, 256>>>(Wg, Wc, WThi, WTlo);
    augru_sort<<<B_ / 256, 256>>>(seqlen, perm, sls);

    cudaFuncSetAttribute(augru_precompute_mma,
                         cudaFuncAttributeMaxDynamicSharedMemorySize, PC_SMEM);
    dim3 gpre(M_ / 128, 3);
    augru_precompute_mma<<<gpre, 256, PC_SMEM>>>(X, WThi, WTlo, seqlen, Gx, Cx);

    cudaFuncSetAttribute(augru_recurrent_tc,
                         cudaFuncAttributeMaxDynamicSharedMemorySize, REC_SMEM);
    augru_recurrent_tc<<<B_ / BPB, THR, REC_SMEM>>>(Gx, Cx, att, perm, sls,
                                                    WThi, WTlo, bg, bc, out);
}